// round 4
// baseline (speedup 1.0000x reference)
#include <cuda_runtime.h>
#include <math.h>

// ---------------------------------------------------------------------------
// WindowAttention fused kernel, round 4: wide register tiles (8ch x 7tok) to
// halve shared-memory lane-byte redundancy; paired half-CTA GEMMs; retiled
// score phase. f32x2 FFMA2 math throughout.
// One CTA per window, 192 threads, ~112KB dynamic smem (2 CTAs/SM).
// ---------------------------------------------------------------------------

#define NTOK   49
#define NCH    96
#define NHEADS 3
#define HDIM   32
#define ST     98               // padded row stride (8B-aligned pairs)
#define AST    50               // attn scratch row stride (even)
#define CST    34               // cattn row stride
#define SCALEF 0.17677669529663687f   // 32^-0.5

#define BUF     (NTOK*ST)                 // 4802
#define OFF_A   0
#define OFF_B   (OFF_A + BUF)
#define OFF_C   (OFF_B + BUF)
#define OFF_D   (OFF_C + BUF)
#define OFF_E   (OFF_D + BUF)
#define OFF_RPB (OFF_E + BUF)             // 507 used, pad 508
#define OFF_NQ  (OFF_RPB + 508)           // 96
#define OFF_NK  (OFF_NQ + 96)             // 96
#define OFF_CAT (OFF_NK + 96)             // 3*32*34 = 3264 (also attn scratch 49*50)
#define SMEM_FLOATS (OFF_CAT + 3264)
#define SMEM_BYTES  (SMEM_FLOATS * 4)     // 111896

typedef unsigned long long u64;

__device__ __forceinline__ u64 dup2(float x) {
    u64 r; asm("mov.b64 %0,{%1,%1};" : "=l"(r) : "f"(x)); return r;
}
__device__ __forceinline__ void fma2(u64& d, u64 a, u64 b) {
    asm("fma.rn.f32x2 %0,%1,%2,%0;" : "+l"(d) : "l"(a), "l"(b));
}
__device__ __forceinline__ float2 unp(u64 a) {
    float2 r; asm("mov.b64 {%0,%1},%2;" : "=f"(r.x), "=f"(r.y) : "l"(a)); return r;
}
__device__ __forceinline__ float hsum(u64 a) {
    float2 p = unp(a); return p.x + p.y;
}
__device__ __forceinline__ u64 lds64(const float* p) {
    return *reinterpret_cast<const u64*>(p);
}

// OUT[49][96] = X[49][96] @ W[96][96] (+bias). 84 threads: 8ch x 7tok tiles.
// lt in [0,84) selects the tile; lt<0 -> inactive.
__device__ __forceinline__ void gemm8(const float* Xs,
                                      const float* __restrict__ W,
                                      const float* __restrict__ bias,
                                      float* Os, int lt)
{
    if (lt < 0) return;
    const int jg = lt / 7, tg = lt % 7;
    const int j0 = jg * 8, t0 = tg * 7;
    u64 acc[7][4];
    #pragma unroll
    for (int t = 0; t < 7; t++)
        #pragma unroll
        for (int i = 0; i < 4; i++) acc[t][i] = 0ULL;
    const ulonglong2* Wr = reinterpret_cast<const ulonglong2*>(W);
    for (int k = 0; k < 96; k += 2) {
        ulonglong2 wa0 = Wr[k * 24 + jg * 2];
        ulonglong2 wa1 = Wr[k * 24 + jg * 2 + 1];
        ulonglong2 wb0 = Wr[(k + 1) * 24 + jg * 2];
        ulonglong2 wb1 = Wr[(k + 1) * 24 + jg * 2 + 1];
        #pragma unroll
        for (int t = 0; t < 7; t++) {
            float2 xp = unp(lds64(Xs + (t0 + t) * ST + k));
            u64 d0 = dup2(xp.x), d1 = dup2(xp.y);
            fma2(acc[t][0], d0, wa0.x); fma2(acc[t][1], d0, wa0.y);
            fma2(acc[t][2], d0, wa1.x); fma2(acc[t][3], d0, wa1.y);
            fma2(acc[t][0], d1, wb0.x); fma2(acc[t][1], d1, wb0.y);
            fma2(acc[t][2], d1, wb1.x); fma2(acc[t][3], d1, wb1.y);
        }
    }
    float bb[8];
    #pragma unroll
    for (int i = 0; i < 8; i++) bb[i] = bias ? bias[j0 + i] : 0.f;
    #pragma unroll
    for (int t = 0; t < 7; t++) {
        float* o = Os + (t0 + t) * ST + j0;
        #pragma unroll
        for (int i = 0; i < 4; i++) {
            float2 a = unp(acc[t][i]);
            o[2 * i]     = a.x + bb[2 * i];
            o[2 * i + 1] = a.y + bb[2 * i + 1];
        }
    }
}

// depthwise 3x3 conv over the 7x7 window, 8ch x 7tok per thread (84 tiles).
// mode 0: out = conv(in) with GELU ; mode 1: out += conv(in)
__device__ __forceinline__ void dwconv8(const float* In, const float* __restrict__ Wc,
                                        float* Out, int lt, int mode)
{
    if (lt < 0) return;
    const int c0 = (lt / 7) * 8, t0 = (lt % 7) * 7;
    u64 wc[9][4];
    #pragma unroll
    for (int s = 0; s < 9; s++) {
        const ulonglong2* wp = reinterpret_cast<const ulonglong2*>(Wc + s * 96 + c0);
        ulonglong2 w0 = wp[0], w1 = wp[1];
        wc[s][0] = w0.x; wc[s][1] = w0.y; wc[s][2] = w1.x; wc[s][3] = w1.y;
    }
    for (int t = t0; t < t0 + 7; t++) {
        int r = t / 7, cc = t % 7;
        u64 a[4] = {0ULL, 0ULL, 0ULL, 0ULL};
        #pragma unroll
        for (int dr = 0; dr < 3; dr++) {
            int rr = r + dr - 1;
            if (rr < 0 || rr > 6) continue;
            #pragma unroll
            for (int dc = 0; dc < 3; dc++) {
                int c2 = cc + dc - 1;
                if (c2 < 0 || c2 > 6) continue;
                const float* vp = In + (rr * 7 + c2) * ST + c0;
                #pragma unroll
                for (int i = 0; i < 4; i++)
                    fma2(a[i], lds64(vp + 2 * i), wc[dr * 3 + dc][i]);
            }
        }
        float* o = Out + t * ST + c0;
        if (mode == 0) {
            #pragma unroll
            for (int i = 0; i < 4; i++) {
                float2 p = unp(a[i]);
                o[2*i]   = 0.5f * p.x * (1.f + erff(p.x * 0.70710678118654752f));
                o[2*i+1] = 0.5f * p.y * (1.f + erff(p.y * 0.70710678118654752f));
            }
        } else {
            #pragma unroll
            for (int i = 0; i < 4; i++) {
                float2 p = unp(a[i]);
                o[2*i] += p.x; o[2*i+1] += p.y;
            }
        }
    }
}

__global__ __launch_bounds__(192, 2) void winattn_kernel(
    const float* __restrict__ x,
    const float* __restrict__ rpb_table,
    const float* __restrict__ wq,    const float* __restrict__ bq,
    const float* __restrict__ wk,    const float* __restrict__ bk,
    const float* __restrict__ wv,    const float* __restrict__ bv,
    const float* __restrict__ w_ps,  const float* __restrict__ b_ps,
    const float* __restrict__ wq_sp, const float* __restrict__ wk_sp,
    const float* __restrict__ w_pc,  const float* __restrict__ b_pc,
    const float* __restrict__ conv1, const float* __restrict__ conv2,
    const float* __restrict__ w_proj,const float* __restrict__ b_proj,
    float* __restrict__ out)
{
    extern __shared__ float sm[];
    float* A   = sm + OFF_A;      // x -> (after ks) spat
    float* Bb  = sm + OFF_B;      // q -> sp -> xc
    float* Cc  = sm + OFF_C;      // k -> ks -> conv1out
    float* Dd  = sm + OFF_D;      // v (whole kernel)
    float* Ee  = sm + OFF_E;      // qs -> out_c/spec
    float* RPB = sm + OFF_RPB;
    float* NQ  = sm + OFF_NQ;
    float* NK  = sm + OFF_NK;
    float* CAT = sm + OFF_CAT;    // attn scratch, later cattn
    float* SCR = CAT;             // 49 x AST attn scores

    const int tid  = threadIdx.x;
    const int blk  = blockIdx.x;
    const int warp = tid >> 5, lane = tid & 31;

    // ---- load x window (float4) + rpb table ----
    {
        const float4* xg4 = reinterpret_cast<const float4*>(x + (size_t)blk * (NTOK * NCH));
        for (int i4 = tid; i4 < NTOK * 24; i4 += 192) {
            float4 v = xg4[i4];
            int t = i4 / 24, c = (i4 % 24) * 4;
            float* p = A + t * ST + c;
            p[0] = v.x; p[1] = v.y; p[2] = v.z; p[3] = v.w;
        }
        for (int i = tid; i < 507; i += 192) RPB[i] = rpb_table[i];
    }
    __syncthreads();

    // ---- paired projections: {q | k}, then {v | qs} ----
    gemm8(A, wq, bq, Bb, (tid < 84) ? tid : -1);
    gemm8(A, wk, bk, Cc, (tid >= 84 && tid < 168) ? tid - 84 : -1);
    __syncthreads();
    gemm8(A, wv, bv, Dd, (tid < 84) ? tid : -1);
    gemm8(A, wq_sp, 0, Ee, (tid >= 84 && tid < 168) ? tid - 84 : -1);
    __syncthreads();

    // ---- spatial attention, per head ----
    for (int h = 0; h < NHEADS; h++) {
        const int ch0 = h * HDIM;
        // scores: 175 threads, 7i x 2j fp32 tiles
        if (tid < 175) {
            int ig = tid / 25, jgr = tid % 25;
            int i0 = ig * 7, j0 = jgr * 2;
            bool j1ok = (j0 + 1) < NTOK;
            float acc[7][2];
            #pragma unroll
            for (int a = 0; a < 7; a++) { acc[a][0] = 0.f; acc[a][1] = 0.f; }
            const float* K0 = Cc + j0 * ST + ch0;
            const float* K1 = Cc + (j0 + (j1ok ? 1 : 0)) * ST + ch0;
            const float* Qb = Bb + i0 * ST + ch0;
            #pragma unroll 4
            for (int d = 0; d < HDIM; d++) {
                float k0 = K0[d], k1 = K1[d];
                #pragma unroll
                for (int a = 0; a < 7; a++) {
                    float qv = Qb[a * ST + d];
                    acc[a][0] += qv * k0;
                    acc[a][1] += qv * k1;
                }
            }
            #pragma unroll
            for (int a = 0; a < 7; a++) {
                int i = i0 + a;
                int r1 = i / 7, c1 = i % 7;
                #pragma unroll
                for (int jj = 0; jj < 2; jj++) {
                    int j = j0 + jj;
                    if (jj == 1 && !j1ok) break;
                    int r2 = j / 7, c2 = j % 7;
                    int ridx = (r1 - r2 + 6) * 13 + (c1 - c2 + 6);
                    SCR[i * AST + j] = acc[a][jj] * SCALEF + RPB[ridx * 3 + h];
                }
            }
        }
        __syncthreads();
        // warp-parallel softmax over 49 rows
        for (int r = warp; r < NTOK; r += 6) {
            float* row = SCR + r * AST;
            float e1 = row[lane];
            bool hi = (lane + 32) < NTOK;
            float e2 = hi ? row[lane + 32] : -3.4e38f;
            float m = fmaxf(e1, e2);
            #pragma unroll
            for (int o = 16; o > 0; o >>= 1) m = fmaxf(m, __shfl_xor_sync(0xffffffffu, m, o));
            float p1 = __expf(e1 - m);
            float p2 = hi ? __expf(e2 - m) : 0.f;
            float s = p1 + p2;
            #pragma unroll
            for (int o = 16; o > 0; o >>= 1) s += __shfl_xor_sync(0xffffffffu, s, o);
            float inv = 1.f / s;
            row[lane] = p1 * inv;
            if (hi) row[lane + 32] = p2 * inv;
        }
        __syncthreads();
        // sp_head = attn @ v_head : 112 threads, 2d x 7tok
        if (tid < 112) {
            int dg = tid / 7, tg = tid % 7;
            int d0 = dg * 2, t0 = tg * 7;
            u64 acc[7];
            #pragma unroll
            for (int t = 0; t < 7; t++) acc[t] = 0ULL;
            #pragma unroll 4
            for (int m = 0; m < 48; m += 2) {
                u64 v2a = lds64(Dd + m * ST + ch0 + d0);
                u64 v2b = lds64(Dd + (m + 1) * ST + ch0 + d0);
                #pragma unroll
                for (int t = 0; t < 7; t++) {
                    float2 ap = unp(lds64(SCR + (t0 + t) * AST + m));
                    fma2(acc[t], dup2(ap.x), v2a);
                    fma2(acc[t], dup2(ap.y), v2b);
                }
            }
            {
                u64 v2a = lds64(Dd + 48 * ST + ch0 + d0);
                #pragma unroll
                for (int t = 0; t < 7; t++)
                    fma2(acc[t], dup2(SCR[(t0 + t) * AST + 48]), v2a);
            }
            #pragma unroll
            for (int t = 0; t < 7; t++)
                *reinterpret_cast<u64*>(Bb + (t0 + t) * ST + ch0 + d0) = acc[t];
        }
        __syncthreads();
    }

    // ---- ks = x @ wk_sp -> C (k dead). x dies after this. ----
    gemm8(A, wk_sp, 0, Cc, (tid < 84) ? tid : -1);
    __syncthreads();

    // ---- paired: {spatial = sp @ w_ps -> A} | {channel norms of qs, ks} ----
    gemm8(Bb, w_ps, b_ps, A, (tid < 84) ? tid : -1);
    if (tid >= 84 && tid < 180) {
        int c = tid - 84;
        float sq = 0.f, sk = 0.f;
        for (int t = 0; t < NTOK; t++) {
            float vq = Ee[t * ST + c]; sq += vq * vq;
            float vk = Cc[t * ST + c]; sk += vk * vk;
        }
        NQ[c] = rsqrtf(fmaxf(sq, 1e-24f));
        NK[c] = rsqrtf(fmaxf(sk, 1e-24f));
    }
    __syncthreads();

    // ---- cattn[h][d][e] raw: 192 threads, 4x4 tiles (ks=C, qs=E) ----
    {
        int h = tid / 64, r = tid % 64;
        int d0 = (r / 8) * 4, e0 = (r % 8) * 4;
        int ch = h * HDIM;
        u64 acc[4][2];
        #pragma unroll
        for (int i = 0; i < 4; i++) { acc[i][0] = 0ULL; acc[i][1] = 0ULL; }
        for (int t = 0; t < NTOK; t++) {
            u64 q0 = lds64(Ee + t * ST + ch + e0);
            u64 q1 = lds64(Ee + t * ST + ch + e0 + 2);
            float2 k01 = unp(lds64(Cc + t * ST + ch + d0));
            float2 k23 = unp(lds64(Cc + t * ST + ch + d0 + 2));
            u64 kd0 = dup2(k01.x), kd1 = dup2(k01.y);
            u64 kd2 = dup2(k23.x), kd3 = dup2(k23.y);
            fma2(acc[0][0], kd0, q0); fma2(acc[0][1], kd0, q1);
            fma2(acc[1][0], kd1, q0); fma2(acc[1][1], kd1, q1);
            fma2(acc[2][0], kd2, q0); fma2(acc[2][1], kd2, q1);
            fma2(acc[3][0], kd3, q0); fma2(acc[3][1], kd3, q1);
        }
        __syncthreads();   // SCR (same memory as CAT) fully consumed above
        #pragma unroll
        for (int i = 0; i < 4; i++) {
            float invk = NK[ch + d0 + i] * SCALEF;
            float2 a0 = unp(acc[i][0]), a1 = unp(acc[i][1]);
            float* o = CAT + h * 1088 + (d0 + i) * CST + e0;
            o[0] = a0.x * invk * NQ[ch + e0 + 0];
            o[1] = a0.y * invk * NQ[ch + e0 + 1];
            o[2] = a1.x * invk * NQ[ch + e0 + 2];
            o[3] = a1.y * invk * NQ[ch + e0 + 3];
        }
    }
    __syncthreads();
    // ---- cattn softmax: warp per row, 96 rows of exactly 32 ----
    for (int rid = warp; rid < 96; rid += 6) {
        float* row = CAT + (rid >> 5) * 1088 + (rid & 31) * CST;
        float e = row[lane];
        float m = e;
        #pragma unroll
        for (int o = 16; o > 0; o >>= 1) m = fmaxf(m, __shfl_xor_sync(0xffffffffu, m, o));
        float p = __expf(e - m);
        float s = p;
        #pragma unroll
        for (int o = 16; o > 0; o >>= 1) s += __shfl_xor_sync(0xffffffffu, s, o);
        row[lane] = p * (1.f / s);
    }
    __syncthreads();

    // ---- xc = cattn @ v (per head) -> B (sp dead). 168 threads. ----
    if (tid < 168) {
        int jg = tid / 7, tg = tid % 7;
        int c0 = jg * 4, t0 = tg * 7;
        int h = c0 / HDIM, d0 = c0 % HDIM, ch = h * HDIM;
        const float* CR = CAT + h * 1088;
        u64 acc[7][4];
        #pragma unroll
        for (int t = 0; t < 7; t++)
            #pragma unroll
            for (int i = 0; i < 4; i++) acc[t][i] = 0ULL;
        #pragma unroll 4
        for (int e = 0; e < HDIM; e += 2) {
            u64 w0 = lds64(CR + (d0 + 0) * CST + e);
            u64 w1 = lds64(CR + (d0 + 1) * CST + e);
            u64 w2 = lds64(CR + (d0 + 2) * CST + e);
            u64 w3 = lds64(CR + (d0 + 3) * CST + e);
            #pragma unroll
            for (int t = 0; t < 7; t++) {
                u64 v2 = lds64(Dd + (t0 + t) * ST + ch + e);
                fma2(acc[t][0], v2, w0);
                fma2(acc[t][1], v2, w1);
                fma2(acc[t][2], v2, w2);
                fma2(acc[t][3], v2, w3);
            }
        }
        #pragma unroll
        for (int t = 0; t < 7; t++) {
            float* o = Bb + (t0 + t) * ST + c0;
            o[0] = hsum(acc[t][0]); o[1] = hsum(acc[t][1]);
            o[2] = hsum(acc[t][2]); o[3] = hsum(acc[t][3]);
        }
    }
    __syncthreads();

    // ---- paired: {out_c = xc @ w_pc -> E} | {conv1(v)+GELU -> C} ----
    gemm8(Bb, w_pc, b_pc, Ee, (tid < 84) ? tid : -1);
    dwconv8(Dd, conv1, Cc, (tid >= 96 && tid < 180) ? tid - 96 : -1, 0);
    __syncthreads();

    // ---- conv2(gelu) -> E += ----
    dwconv8(Cc, conv2, Ee, (tid < 84) ? tid : -1, 1);
    __syncthreads();

    // ---- final: out = spat(A) @ Wp[0:96] + spec(E) @ Wp[96:192] + b_proj ----
    if (tid < 84) {
        int jg = tid / 7, tg = tid % 7;
        int j0 = jg * 8, t0 = tg * 7;
        u64 acc[7][4];
        #pragma unroll
        for (int t = 0; t < 7; t++)
            #pragma unroll
            for (int i = 0; i < 4; i++) acc[t][i] = 0ULL;
        const ulonglong2* Wr = reinterpret_cast<const ulonglong2*>(w_proj);
        for (int k = 0; k < 96; k += 2) {
            ulonglong2 a0 = Wr[k * 24 + jg * 2];
            ulonglong2 a1 = Wr[k * 24 + jg * 2 + 1];
            ulonglong2 a2 = Wr[(k + 1) * 24 + jg * 2];
            ulonglong2 a3 = Wr[(k + 1) * 24 + jg * 2 + 1];
            ulonglong2 b0 = Wr[(k + 96) * 24 + jg * 2];
            ulonglong2 b1 = Wr[(k + 96) * 24 + jg * 2 + 1];
            ulonglong2 b2 = Wr[(k + 97) * 24 + jg * 2];
            ulonglong2 b3 = Wr[(k + 97) * 24 + jg * 2 + 1];
            #pragma unroll
            for (int t = 0; t < 7; t++) {
                float2 sa = unp(lds64(A  + (t0 + t) * ST + k));
                float2 sb = unp(lds64(Ee + (t0 + t) * ST + k));
                u64 da0 = dup2(sa.x), da1 = dup2(sa.y);
                u64 db0 = dup2(sb.x), db1 = dup2(sb.y);
                fma2(acc[t][0], da0, a0.x); fma2(acc[t][1], da0, a0.y);
                fma2(acc[t][2], da0, a1.x); fma2(acc[t][3], da0, a1.y);
                fma2(acc[t][0], da1, a2.x); fma2(acc[t][1], da1, a2.y);
                fma2(acc[t][2], da1, a3.x); fma2(acc[t][3], da1, a3.y);
                fma2(acc[t][0], db0, b0.x); fma2(acc[t][1], db0, b0.y);
                fma2(acc[t][2], db0, b1.x); fma2(acc[t][3], db0, b1.y);
                fma2(acc[t][0], db1, b2.x); fma2(acc[t][1], db1, b2.y);
                fma2(acc[t][2], db1, b3.x); fma2(acc[t][3], db1, b3.y);
            }
        }
        float4 bb0 = *reinterpret_cast<const float4*>(b_proj + j0);
        float4 bb1 = *reinterpret_cast<const float4*>(b_proj + j0 + 4);
        float* og = out + (size_t)blk * (NTOK * NCH);
        #pragma unroll
        for (int t = 0; t < 7; t++) {
            float2 a0 = unp(acc[t][0]), a1 = unp(acc[t][1]);
            float2 a2 = unp(acc[t][2]), a3 = unp(acc[t][3]);
            float4 r0, r1;
            r0.x = a0.x + bb0.x; r0.y = a0.y + bb0.y;
            r0.z = a1.x + bb0.z; r0.w = a1.y + bb0.w;
            r1.x = a2.x + bb1.x; r1.y = a2.y + bb1.y;
            r1.z = a3.x + bb1.z; r1.w = a3.y + bb1.w;
            float* op = og + (t0 + t) * NCH + j0;
            *reinterpret_cast<float4*>(op)     = r0;
            *reinterpret_cast<float4*>(op + 4) = r1;
        }
    }
}

extern "C" void kernel_launch(void* const* d_in, const int* in_sizes, int n_in,
                              void* d_out, int out_size)
{
    const float* x      = (const float*)d_in[0];
    const float* rpb    = (const float*)d_in[1];
    const float* wq     = (const float*)d_in[2];
    const float* bq     = (const float*)d_in[3];
    const float* wk     = (const float*)d_in[4];
    const float* bk     = (const float*)d_in[5];
    const float* wv     = (const float*)d_in[6];
    const float* bv     = (const float*)d_in[7];
    const float* w_ps   = (const float*)d_in[8];
    const float* b_ps   = (const float*)d_in[9];
    const float* wq_sp  = (const float*)d_in[10];
    const float* wk_sp  = (const float*)d_in[11];
    const float* w_pc   = (const float*)d_in[12];
    const float* b_pc   = (const float*)d_in[13];
    const float* conv1  = (const float*)d_in[14];
    const float* conv2  = (const float*)d_in[15];
    const float* w_proj = (const float*)d_in[16];
    const float* b_proj = (const float*)d_in[17];
    float* out = (float*)d_out;

    int nwin = in_sizes[0] / (NTOK * NCH);

    cudaFuncSetAttribute(winattn_kernel,
                         cudaFuncAttributeMaxDynamicSharedMemorySize, SMEM_BYTES);
    winattn_kernel<<<nwin, 192, SMEM_BYTES>>>(
        x, rpb, wq, bq, wk, bk, wv, bv, w_ps, b_ps,
        wq_sp, wk_sp, w_pc, b_pc, conv1, conv2, w_proj, b_proj, out);
}

// round 5
// speedup vs baseline: 1.1837x; 1.1837x over previous
#include <cuda_runtime.h>
#include <math.h>

// ---------------------------------------------------------------------------
// WindowAttention fused kernel, round 5: R3 algorithms, retiled for 256
// threads/CTA -> 16 warps/SM at 2 CTAs/SM (was 12). f32x2 FFMA2 + LDS.64.
// ---------------------------------------------------------------------------

#define NTOK   49
#define NCH    96
#define NHEADS 3
#define HDIM   32
#define ST     98               // padded row stride (8B-aligned pairs)
#define AST    50               // attn scratch row stride (even)
#define CST    34               // cattn row stride
#define SCALEF 0.17677669529663687f   // 32^-0.5
#define NTHR   256

#define BUF     (NTOK*ST)                 // 4802
#define OFF_A   0
#define OFF_B   (OFF_A + BUF)
#define OFF_C   (OFF_B + BUF)
#define OFF_D   (OFF_C + BUF)
#define OFF_E   (OFF_D + BUF)
#define OFF_RPB (OFF_E + BUF)             // 507 used, pad 508
#define OFF_NQ  (OFF_RPB + 508)           // 96
#define OFF_NK  (OFF_NQ + 96)             // 96
#define OFF_CAT (OFF_NK + 96)             // 3*32*34 = 3264
#define SMEM_FLOATS (OFF_CAT + 3264)
#define SMEM_BYTES  (SMEM_FLOATS * 4)     // 111896

typedef unsigned long long u64;

__device__ __forceinline__ u64 dup2(float x) {
    u64 r; asm("mov.b64 %0,{%1,%1};" : "=l"(r) : "f"(x)); return r;
}
__device__ __forceinline__ void fma2(u64& d, u64 a, u64 b) {
    asm("fma.rn.f32x2 %0,%1,%2,%0;" : "+l"(d) : "l"(a), "l"(b));
}
__device__ __forceinline__ float2 unp(u64 a) {
    float2 r; asm("mov.b64 {%0,%1},%2;" : "=f"(r.x), "=f"(r.y) : "l"(a)); return r;
}
__device__ __forceinline__ float hsum(u64 a) {
    float2 p = unp(a); return p.x + p.y;
}
__device__ __forceinline__ u64 lds64(const float* p) {
    return *reinterpret_cast<const u64*>(p);
}

// OUT[49][96] = X[49][96] @ W[96][96] (+bias). 240 threads: 4ch x 5tok tiles.
// Stores guarded for the ragged token tail (tg=9 covers 4 real tokens).
__device__ __forceinline__ void gemm5(const float* Xs,
                                      const float* __restrict__ W,
                                      const float* __restrict__ bias,
                                      float* Os, int tid)
{
    if (tid >= 240) return;
    const int jg = tid / 10, tg = tid % 10;
    const int j0 = jg * 4, t0 = tg * 5;
    u64 acc[5][2];
    #pragma unroll
    for (int t = 0; t < 5; t++) { acc[t][0] = 0ULL; acc[t][1] = 0ULL; }
    const ulonglong2* Wr = reinterpret_cast<const ulonglong2*>(W);
    #pragma unroll 2
    for (int k = 0; k < 96; k += 2) {
        ulonglong2 w0 = Wr[k * 24 + jg];
        ulonglong2 w1 = Wr[(k + 1) * 24 + jg];
        #pragma unroll
        for (int t = 0; t < 5; t++) {
            float2 xp = unp(lds64(Xs + (t0 + t) * ST + k));
            u64 d0 = dup2(xp.x), d1 = dup2(xp.y);
            fma2(acc[t][0], d0, w0.x);
            fma2(acc[t][1], d0, w0.y);
            fma2(acc[t][0], d1, w1.x);
            fma2(acc[t][1], d1, w1.y);
        }
    }
    float2 b01 = make_float2(0.f, 0.f), b23 = make_float2(0.f, 0.f);
    if (bias) {
        b01 = *reinterpret_cast<const float2*>(bias + j0);
        b23 = *reinterpret_cast<const float2*>(bias + j0 + 2);
    }
    #pragma unroll
    for (int t = 0; t < 5; t++) {
        if (t0 + t < NTOK) {
            float2 a0 = unp(acc[t][0]), a1 = unp(acc[t][1]);
            float* o = Os + (t0 + t) * ST + j0;
            o[0] = a0.x + b01.x; o[1] = a0.y + b01.y;
            o[2] = a1.x + b23.x; o[3] = a1.y + b23.y;
        }
    }
}

// depthwise 3x3 conv, 4ch x 5tok per thread (240 active).
// mode 0: out = GELU(conv(in)) ; mode 1: out += conv(in)
__device__ __forceinline__ void dwconv5(const float* In, const float* __restrict__ Wc,
                                        float* Out, int tid, int mode)
{
    if (tid >= 240) return;
    const int c0 = (tid / 10) * 4, t0 = (tid % 10) * 5;
    u64 wc[9][2];
    #pragma unroll
    for (int s = 0; s < 9; s++) {
        const ulonglong2* wp = reinterpret_cast<const ulonglong2*>(Wc + s * 96 + c0);
        ulonglong2 w = *wp;
        wc[s][0] = w.x; wc[s][1] = w.y;
    }
    #pragma unroll
    for (int tt = 0; tt < 5; tt++) {
        int t = t0 + tt;
        if (t >= NTOK) break;
        int r = t / 7, cc = t % 7;
        u64 a0 = 0ULL, a1 = 0ULL;
        #pragma unroll
        for (int dr = 0; dr < 3; dr++) {
            int rr = r + dr - 1;
            if (rr < 0 || rr > 6) continue;
            #pragma unroll
            for (int dc = 0; dc < 3; dc++) {
                int c2 = cc + dc - 1;
                if (c2 < 0 || c2 > 6) continue;
                const float* vp = In + (rr * 7 + c2) * ST + c0;
                fma2(a0, lds64(vp), wc[dr * 3 + dc][0]);
                fma2(a1, lds64(vp + 2), wc[dr * 3 + dc][1]);
            }
        }
        float2 p0 = unp(a0), p1 = unp(a1);
        float* o = Out + t * ST + c0;
        if (mode == 0) {
            o[0] = 0.5f * p0.x * (1.f + erff(p0.x * 0.70710678118654752f));
            o[1] = 0.5f * p0.y * (1.f + erff(p0.y * 0.70710678118654752f));
            o[2] = 0.5f * p1.x * (1.f + erff(p1.x * 0.70710678118654752f));
            o[3] = 0.5f * p1.y * (1.f + erff(p1.y * 0.70710678118654752f));
        } else {
            o[0] += p0.x; o[1] += p0.y; o[2] += p1.x; o[3] += p1.y;
        }
    }
}

__global__ __launch_bounds__(NTHR, 2) void winattn_kernel(
    const float* __restrict__ x,
    const float* __restrict__ rpb_table,
    const float* __restrict__ wq,    const float* __restrict__ bq,
    const float* __restrict__ wk,    const float* __restrict__ bk,
    const float* __restrict__ wv,    const float* __restrict__ bv,
    const float* __restrict__ w_ps,  const float* __restrict__ b_ps,
    const float* __restrict__ wq_sp, const float* __restrict__ wk_sp,
    const float* __restrict__ w_pc,  const float* __restrict__ b_pc,
    const float* __restrict__ conv1, const float* __restrict__ conv2,
    const float* __restrict__ w_proj,const float* __restrict__ b_proj,
    float* __restrict__ out)
{
    extern __shared__ float sm[];
    float* A   = sm + OFF_A;      // x -> xc
    float* Bb  = sm + OFF_B;      // q -> sp -> ks -> conv1out
    float* Cc  = sm + OFF_C;      // k -> spat
    float* Dd  = sm + OFF_D;      // v (whole kernel)
    float* Ee  = sm + OFF_E;      // attn scratch -> qs -> out_c/spec
    float* RPB = sm + OFF_RPB;
    float* NQ  = sm + OFF_NQ;
    float* NK  = sm + OFF_NK;
    float* CAT = sm + OFF_CAT;

    const int tid  = threadIdx.x;
    const int blk  = blockIdx.x;
    const int warp = tid >> 5, lane = tid & 31;

    // ---- load x window (float4) + rpb table ----
    {
        const float4* xg4 = reinterpret_cast<const float4*>(x + (size_t)blk * (NTOK * NCH));
        for (int i4 = tid; i4 < NTOK * 24; i4 += NTHR) {
            float4 v = xg4[i4];
            int t = i4 / 24, c = (i4 % 24) * 4;
            float* p = A + t * ST + c;
            p[0] = v.x; p[1] = v.y; p[2] = v.z; p[3] = v.w;
        }
        for (int i = tid; i < 507; i += NTHR) RPB[i] = rpb_table[i];
    }
    __syncthreads();

    // ---- q, k, v projections ----
    gemm5(A, wq, bq, Bb, tid);
    __syncthreads();
    gemm5(A, wk, bk, Cc, tid);
    __syncthreads();
    gemm5(A, wv, bv, Dd, tid);
    __syncthreads();

    // ---- spatial attention, per head ----
    for (int h = 0; h < NHEADS; h++) {
        const int ch0 = h * HDIM;
        // scores: 7i x 1j tiles, strided over 343 units
        for (int idx = tid; idx < 7 * NTOK; idx += NTHR) {
            int ig = idx / NTOK, j = idx % NTOK;
            int i0 = ig * 7;
            u64 acc[7];
            #pragma unroll
            for (int a = 0; a < 7; a++) acc[a] = 0ULL;
            const float* Kj = Cc + j * ST + ch0;
            const float* Qb = Bb + i0 * ST + ch0;
            #pragma unroll
            for (int d = 0; d < HDIM; d += 2) {
                u64 k2 = lds64(Kj + d);
                #pragma unroll
                for (int a = 0; a < 7; a++)
                    fma2(acc[a], lds64(Qb + a * ST + d), k2);
            }
            int r2 = j / 7, c2 = j % 7;
            #pragma unroll
            for (int a = 0; a < 7; a++) {
                int i = i0 + a;
                int r1 = i / 7, c1 = i % 7;
                int ridx = (r1 - r2 + 6) * 13 + (c1 - c2 + 6);
                Ee[i * AST + j] = hsum(acc[a]) * SCALEF + RPB[ridx * 3 + h];
            }
        }
        __syncthreads();
        // warp-parallel softmax over 49 rows (8 warps)
        for (int r = warp; r < NTOK; r += 8) {
            float* row = Ee + r * AST;
            float e1 = row[lane];
            bool hi = (lane + 32) < NTOK;
            float e2 = hi ? row[lane + 32] : -3.4e38f;
            float m = fmaxf(e1, e2);
            #pragma unroll
            for (int o = 16; o > 0; o >>= 1) m = fmaxf(m, __shfl_xor_sync(0xffffffffu, m, o));
            float p1 = __expf(e1 - m);
            float p2 = hi ? __expf(e2 - m) : 0.f;
            float s = p1 + p2;
            #pragma unroll
            for (int o = 16; o > 0; o >>= 1) s += __shfl_xor_sync(0xffffffffu, s, o);
            float inv = 1.f / s;
            row[lane] = p1 * inv;
            if (hi) row[lane + 32] = p2 * inv;
        }
        __syncthreads();
        // sp_head = attn @ v_head : 224 threads, 1d x 7tok
        if (tid < 224) {
            int dg = tid / 7, tg = tid % 7;
            int t0 = tg * 7;
            float accs[7];
            #pragma unroll
            for (int t = 0; t < 7; t++) accs[t] = 0.f;
            u64 acc[7];
            #pragma unroll
            for (int t = 0; t < 7; t++) acc[t] = 0ULL;
            #pragma unroll 4
            for (int m = 0; m < 48; m += 2) {
                float va = Dd[m * ST + ch0 + dg];
                float vb = Dd[(m + 1) * ST + ch0 + dg];
                u64 v2; asm("mov.b64 %0,{%1,%2};" : "=l"(v2) : "f"(va), "f"(vb));
                #pragma unroll
                for (int t = 0; t < 7; t++)
                    fma2(acc[t], lds64(Ee + (t0 + t) * AST + m), v2);
            }
            {
                float va = Dd[48 * ST + ch0 + dg];
                #pragma unroll
                for (int t = 0; t < 7; t++)
                    accs[t] = Ee[(t0 + t) * AST + 48] * va;
            }
            #pragma unroll
            for (int t = 0; t < 7; t++)
                Bb[(t0 + t) * ST + ch0 + dg] = hsum(acc[t]) + accs[t];
        }
        __syncthreads();
    }

    // ---- spatial_x = sp @ w_ps + b_ps -> C ----
    gemm5(Bb, w_ps, b_ps, Cc, tid);
    __syncthreads();
    gemm5(A, wq_sp, 0, Ee, tid);      // qs -> E
    __syncthreads();
    gemm5(A, wk_sp, 0, Bb, tid);      // ks -> B
    __syncthreads();

    // ---- inverse L2 norms per channel ----
    if (tid < 96) {
        float s = 0.f;
        for (int t = 0; t < NTOK; t++) { float v = Ee[t * ST + tid]; s += v * v; }
        NQ[tid] = rsqrtf(fmaxf(s, 1e-24f));
    } else if (tid < 192) {
        int c = tid - 96;
        float s = 0.f;
        for (int t = 0; t < NTOK; t++) { float v = Bb[t * ST + c]; s += v * v; }
        NK[c] = rsqrtf(fmaxf(s, 1e-24f));
    }
    __syncthreads();

    // ---- cattn[h][d][e] raw: 192 active, 4x4 tiles (ks=B, qs=E) ----
    if (tid < 192) {
        int h = tid / 64, r = tid % 64;
        int d0 = (r / 8) * 4, e0 = (r % 8) * 4;
        int ch = h * HDIM;
        u64 acc[4][2];
        #pragma unroll
        for (int i = 0; i < 4; i++) { acc[i][0] = 0ULL; acc[i][1] = 0ULL; }
        for (int t = 0; t < NTOK; t++) {
            u64 q0 = lds64(Ee + t * ST + ch + e0);
            u64 q1 = lds64(Ee + t * ST + ch + e0 + 2);
            float2 k01 = unp(lds64(Bb + t * ST + ch + d0));
            float2 k23 = unp(lds64(Bb + t * ST + ch + d0 + 2));
            u64 kd0 = dup2(k01.x), kd1 = dup2(k01.y);
            u64 kd2 = dup2(k23.x), kd3 = dup2(k23.y);
            fma2(acc[0][0], kd0, q0); fma2(acc[0][1], kd0, q1);
            fma2(acc[1][0], kd1, q0); fma2(acc[1][1], kd1, q1);
            fma2(acc[2][0], kd2, q0); fma2(acc[2][1], kd2, q1);
            fma2(acc[3][0], kd3, q0); fma2(acc[3][1], kd3, q1);
        }
        #pragma unroll
        for (int i = 0; i < 4; i++) {
            float invk = NK[ch + d0 + i] * SCALEF;
            float2 a0 = unp(acc[i][0]), a1 = unp(acc[i][1]);
            float* o = CAT + h * 1088 + (d0 + i) * CST + e0;
            o[0] = a0.x * invk * NQ[ch + e0 + 0];
            o[1] = a0.y * invk * NQ[ch + e0 + 1];
            o[2] = a1.x * invk * NQ[ch + e0 + 2];
            o[3] = a1.y * invk * NQ[ch + e0 + 3];
        }
    }
    __syncthreads();
    // ---- cattn softmax: warp per row, 96 rows of 32 (8 warps) ----
    for (int rid = warp; rid < 96; rid += 8) {
        float* row = CAT + (rid >> 5) * 1088 + (rid & 31) * CST;
        float e = row[lane];
        float m = e;
        #pragma unroll
        for (int o = 16; o > 0; o >>= 1) m = fmaxf(m, __shfl_xor_sync(0xffffffffu, m, o));
        float p = __expf(e - m);
        float s = p;
        #pragma unroll
        for (int o = 16; o > 0; o >>= 1) s += __shfl_xor_sync(0xffffffffu, s, o);
        row[lane] = p * (1.f / s);
    }
    __syncthreads();

    // ---- xc = cattn @ v -> A. 240 threads, 4ch x 5tok ----
    if (tid < 240) {
        int jg = tid / 10, tg = tid % 10;
        int c0 = jg * 4, t0 = tg * 5;
        int h = c0 / HDIM, d0 = c0 % HDIM, ch = h * HDIM;
        const float* CR = CAT + h * 1088;
        u64 acc[5][4];
        #pragma unroll
        for (int t = 0; t < 5; t++)
            #pragma unroll
            for (int i = 0; i < 4; i++) acc[t][i] = 0ULL;
        #pragma unroll 4
        for (int e = 0; e < HDIM; e += 2) {
            u64 w0 = lds64(CR + (d0 + 0) * CST + e);
            u64 w1 = lds64(CR + (d0 + 1) * CST + e);
            u64 w2 = lds64(CR + (d0 + 2) * CST + e);
            u64 w3 = lds64(CR + (d0 + 3) * CST + e);
            #pragma unroll
            for (int t = 0; t < 5; t++) {
                u64 v2 = lds64(Dd + (t0 + t) * ST + ch + e);
                fma2(acc[t][0], v2, w0);
                fma2(acc[t][1], v2, w1);
                fma2(acc[t][2], v2, w2);
                fma2(acc[t][3], v2, w3);
            }
        }
        #pragma unroll
        for (int t = 0; t < 5; t++) {
            if (t0 + t < NTOK) {
                float* o = A + (t0 + t) * ST + c0;
                o[0] = hsum(acc[t][0]); o[1] = hsum(acc[t][1]);
                o[2] = hsum(acc[t][2]); o[3] = hsum(acc[t][3]);
            }
        }
    }
    __syncthreads();

    // ---- out_c = xc @ w_pc + b_pc -> E ----
    gemm5(A, w_pc, b_pc, Ee, tid);
    __syncthreads();

    // ---- conv1(v) + GELU -> B ----
    dwconv5(Dd, conv1, Bb, tid, 0);
    __syncthreads();

    // ---- conv2(gelu) -> E += ----
    dwconv5(Bb, conv2, Ee, tid, 1);
    __syncthreads();

    // ---- final: out = spat(C) @ Wp[0:96] + spec(E) @ Wp[96:192] + b_proj ----
    if (tid < 240) {
        int jg = tid / 10, tg = tid % 10;
        int j0 = jg * 4, t0 = tg * 5;
        u64 acc[5][2];
        #pragma unroll
        for (int t = 0; t < 5; t++) { acc[t][0] = 0ULL; acc[t][1] = 0ULL; }
        const ulonglong2* Wr = reinterpret_cast<const ulonglong2*>(w_proj);
        for (int k = 0; k < 96; k += 2) {
            ulonglong2 wa0 = Wr[k * 24 + jg];
            ulonglong2 wa1 = Wr[(k + 1) * 24 + jg];
            ulonglong2 wb0 = Wr[(k + 96) * 24 + jg];
            ulonglong2 wb1 = Wr[(k + 97) * 24 + jg];
            #pragma unroll
            for (int t = 0; t < 5; t++) {
                float2 sa = unp(lds64(Cc + (t0 + t) * ST + k));
                float2 sb = unp(lds64(Ee + (t0 + t) * ST + k));
                fma2(acc[t][0], dup2(sa.x), wa0.x);
                fma2(acc[t][1], dup2(sa.x), wa0.y);
                fma2(acc[t][0], dup2(sa.y), wa1.x);
                fma2(acc[t][1], dup2(sa.y), wa1.y);
                fma2(acc[t][0], dup2(sb.x), wb0.x);
                fma2(acc[t][1], dup2(sb.x), wb0.y);
                fma2(acc[t][0], dup2(sb.y), wb1.x);
                fma2(acc[t][1], dup2(sb.y), wb1.y);
            }
        }
        float2 b01 = *reinterpret_cast<const float2*>(b_proj + j0);
        float2 b23 = *reinterpret_cast<const float2*>(b_proj + j0 + 2);
        float* og = out + (size_t)blk * (NTOK * NCH);
        #pragma unroll
        for (int t = 0; t < 5; t++) {
            if (t0 + t < NTOK) {
                float2 a0 = unp(acc[t][0]), a1 = unp(acc[t][1]);
                float4 r;
                r.x = a0.x + b01.x; r.y = a0.y + b01.y;
                r.z = a1.x + b23.x; r.w = a1.y + b23.y;
                *reinterpret_cast<float4*>(og + (t0 + t) * NCH + j0) = r;
            }
        }
    }
}

extern "C" void kernel_launch(void* const* d_in, const int* in_sizes, int n_in,
                              void* d_out, int out_size)
{
    const float* x      = (const float*)d_in[0];
    const float* rpb    = (const float*)d_in[1];
    const float* wq     = (const float*)d_in[2];
    const float* bq     = (const float*)d_in[3];
    const float* wk     = (const float*)d_in[4];
    const float* bk     = (const float*)d_in[5];
    const float* wv     = (const float*)d_in[6];
    const float* bv     = (const float*)d_in[7];
    const float* w_ps   = (const float*)d_in[8];
    const float* b_ps   = (const float*)d_in[9];
    const float* wq_sp  = (const float*)d_in[10];
    const float* wk_sp  = (const float*)d_in[11];
    const float* w_pc   = (const float*)d_in[12];
    const float* b_pc   = (const float*)d_in[13];
    const float* conv1  = (const float*)d_in[14];
    const float* conv2  = (const float*)d_in[15];
    const float* w_proj = (const float*)d_in[16];
    const float* b_proj = (const float*)d_in[17];
    float* out = (float*)d_out;

    int nwin = in_sizes[0] / (NTOK * NCH);

    cudaFuncSetAttribute(winattn_kernel,
                         cudaFuncAttributeMaxDynamicSharedMemorySize, SMEM_BYTES);
    winattn_kernel<<<nwin, NTHR, SMEM_BYTES>>>(
        x, rpb, wq, bq, wk, bk, wv, bv, w_ps, b_ps,
        wq_sp, wk_sp, w_pc, b_pc, conv1, conv2, w_proj, b_proj, out);
}

// round 7
// speedup vs baseline: 1.2261x; 1.0358x over previous
#include <cuda_runtime.h>
#include <math.h>
#include <stdint.h>

// ---------------------------------------------------------------------------
// WindowAttention fused kernel, round 7: bf16 split (hi/lo) m16n8k16 mma.sync
// for all dense GEMMs; weights pre-split to __device__ globals by a prologue
// kernel. Irregular phases stay FFMA2+LDS.64 (R5). 256 thr, 2 CTAs/SM.
// ---------------------------------------------------------------------------

#define NTOK   49
#define NCH    96
#define NHEADS 3
#define HDIM   32
#define ST     98
#define AST    50
#define CST    34
#define SCALEF 0.17677669529663687f
#define NTHR   256

#define BUF     (NTOK*ST)
#define OFF_A   0
#define OFF_B   (OFF_A + BUF)
#define OFF_C   (OFF_B + BUF)
#define OFF_D   (OFF_C + BUF)
#define OFF_E   (OFF_D + BUF)
#define OFF_RPB (OFF_E + BUF)
#define OFF_NQ  (OFF_RPB + 508)
#define OFF_NK  (OFF_NQ + 96)
#define OFF_CAT (OFF_NK + 96)
#define SMEM_FLOATS (OFF_CAT + 3264)
#define SMEM_BYTES  (SMEM_FLOATS * 4)     // 111896

// pre-split weight storage: k-pair-packed bf16x2, [K/2][96] per matrix
#define WQ_OFF    0
#define WK_OFF    4608
#define WV_OFF    9216
#define WPS_OFF   13824
#define WQSP_OFF  18432
#define WKSP_OFF  23040
#define WPC_OFF   27648
#define WPROJ_OFF 32256
#define WTOT      41472

__device__ uint32_t g_whi[WTOT];
__device__ uint32_t g_wlo[WTOT];

typedef unsigned long long u64;

__device__ __forceinline__ u64 dup2(float x) {
    u64 r; asm("mov.b64 %0,{%1,%1};" : "=l"(r) : "f"(x)); return r;
}
__device__ __forceinline__ void fma2(u64& d, u64 a, u64 b) {
    asm("fma.rn.f32x2 %0,%1,%2,%0;" : "+l"(d) : "l"(a), "l"(b));
}
__device__ __forceinline__ float2 unp(u64 a) {
    float2 r; asm("mov.b64 {%0,%1},%2;" : "=f"(r.x), "=f"(r.y) : "l"(a)); return r;
}
__device__ __forceinline__ float hsum(u64 a) {
    float2 p = unp(a); return p.x + p.y;
}
__device__ __forceinline__ u64 lds64(const float* p) {
    return *reinterpret_cast<const u64*>(p);
}
// pack {lo=first(l), hi=second(h)} into bf16x2
__device__ __forceinline__ uint32_t cvtbf2(float h, float l) {
    uint32_t r; asm("cvt.rn.bf16x2.f32 %0, %1, %2;" : "=r"(r) : "f"(h), "f"(l)); return r;
}
__device__ __forceinline__ float blo2f(uint32_t p) { return __uint_as_float(p << 16); }
__device__ __forceinline__ float bhi2f(uint32_t p) { return __uint_as_float(p & 0xFFFF0000u); }

__device__ __forceinline__ void mma16(float d[4],
                                      uint32_t a0, uint32_t a1, uint32_t a2, uint32_t a3,
                                      uint32_t b0, uint32_t b1) {
    asm volatile("mma.sync.aligned.m16n8k16.row.col.f32.bf16.bf16.f32 "
                 "{%0,%1,%2,%3}, {%4,%5,%6,%7}, {%8,%9}, {%0,%1,%2,%3};"
                 : "+f"(d[0]), "+f"(d[1]), "+f"(d[2]), "+f"(d[3])
                 : "r"(a0), "r"(a1), "r"(a2), "r"(a3), "r"(b0), "r"(b1));
}

// ---------------- prologue: split weights into bf16 hi/lo k-pair packs ------
__global__ void prep_weights(const float* __restrict__ wq, const float* __restrict__ wk,
                             const float* __restrict__ wv, const float* __restrict__ w_ps,
                             const float* __restrict__ wq_sp, const float* __restrict__ wk_sp,
                             const float* __restrict__ w_pc, const float* __restrict__ w_proj)
{
    int idx = blockIdx.x * 256 + threadIdx.x;
    if (idx >= WTOT) return;
    const float* W; int base;
    if      (idx < WK_OFF)    { W = wq;     base = WQ_OFF; }
    else if (idx < WV_OFF)    { W = wk;     base = WK_OFF; }
    else if (idx < WPS_OFF)   { W = wv;     base = WV_OFF; }
    else if (idx < WQSP_OFF)  { W = w_ps;   base = WPS_OFF; }
    else if (idx < WKSP_OFF)  { W = wq_sp;  base = WQSP_OFF; }
    else if (idx < WPC_OFF)   { W = wk_sp;  base = WKSP_OFF; }
    else if (idx < WPROJ_OFF) { W = w_pc;   base = WPC_OFF; }
    else                      { W = w_proj; base = WPROJ_OFF; }
    int local = idx - base;
    int kp = local / 96, n = local % 96;
    float x0 = W[(2 * kp) * 96 + n];
    float x1 = W[(2 * kp + 1) * 96 + n];
    uint32_t hi = cvtbf2(x1, x0);                 // low half = x0 (even k)
    uint32_t lo = cvtbf2(x1 - bhi2f(hi), x0 - blo2f(hi));
    g_whi[idx] = hi;
    g_wlo[idx] = lo;
}

// ---- bf16-split GEMM: OUT[49][96](ST) = X[49][96](ST) @ W + bias ----------
// 8 warps: m-tile = warp>>1, n-half = warp&1 (6 n-tiles of 8).
__device__ __forceinline__ void gemm_bf16(const float* Xs, int wbase,
                                          const float* __restrict__ bias, float* Os,
                                          int warp, int lane)
{
    const int m0 = (warp >> 1) * 16;
    const int n0 = (warp & 1) * 48;
    const int gid = lane >> 2, tig = lane & 3;
    float d[6][4];
    #pragma unroll
    for (int i = 0; i < 6; i++) { d[i][0] = d[i][1] = d[i][2] = d[i][3] = 0.f; }
    const float* Xr0 = Xs + (m0 + gid) * ST;
    const float* Xr1 = Xs + (m0 + gid + 8) * ST;
    #pragma unroll
    for (int kc = 0; kc < 6; kc++) {
        const int kp = kc * 8 + tig;
        float2 p00 = *reinterpret_cast<const float2*>(Xr0 + 2 * kp);
        float2 p10 = *reinterpret_cast<const float2*>(Xr1 + 2 * kp);
        float2 p01 = *reinterpret_cast<const float2*>(Xr0 + 2 * (kp + 4));
        float2 p11 = *reinterpret_cast<const float2*>(Xr1 + 2 * (kp + 4));
        uint32_t a0h = cvtbf2(p00.y, p00.x);
        uint32_t a1h = cvtbf2(p10.y, p10.x);
        uint32_t a2h = cvtbf2(p01.y, p01.x);
        uint32_t a3h = cvtbf2(p11.y, p11.x);
        uint32_t a0l = cvtbf2(p00.y - bhi2f(a0h), p00.x - blo2f(a0h));
        uint32_t a1l = cvtbf2(p10.y - bhi2f(a1h), p10.x - blo2f(a1h));
        uint32_t a2l = cvtbf2(p01.y - bhi2f(a2h), p01.x - blo2f(a2h));
        uint32_t a3l = cvtbf2(p11.y - bhi2f(a3h), p11.x - blo2f(a3h));
        const uint32_t* Bh0 = g_whi + wbase + kp * 96 + n0 + gid;
        const uint32_t* Bh1 = g_whi + wbase + (kp + 4) * 96 + n0 + gid;
        const uint32_t* Bl0 = g_wlo + wbase + kp * 96 + n0 + gid;
        const uint32_t* Bl1 = g_wlo + wbase + (kp + 4) * 96 + n0 + gid;
        #pragma unroll
        for (int nt = 0; nt < 6; nt++) {
            uint32_t b0h = Bh0[nt * 8], b1h = Bh1[nt * 8];
            uint32_t b0l = Bl0[nt * 8], b1l = Bl1[nt * 8];
            mma16(d[nt], a0h, a1h, a2h, a3h, b0h, b1h);
            mma16(d[nt], a0h, a1h, a2h, a3h, b0l, b1l);
            mma16(d[nt], a0l, a1l, a2l, a3l, b0h, b1h);
        }
    }
    const int r0 = m0 + gid, r1 = m0 + gid + 8;
    #pragma unroll
    for (int nt = 0; nt < 6; nt++) {
        int n = n0 + nt * 8 + tig * 2;
        float bx = 0.f, by = 0.f;
        if (bias) { bx = bias[n]; by = bias[n + 1]; }
        if (r0 < NTOK) { float* o = Os + r0 * ST + n; o[0] = d[nt][0] + bx; o[1] = d[nt][1] + by; }
        if (r1 < NTOK) { float* o = Os + r1 * ST + n; o[0] = d[nt][2] + bx; o[1] = d[nt][3] + by; }
    }
}

// ---- final projection: out = [Sa|Sb](K=192) @ w_proj + b_proj (global out) --
__device__ __forceinline__ void proj_bf16(const float* Sa, const float* Sb,
                                          const float* __restrict__ bias,
                                          float* __restrict__ og, int warp, int lane)
{
    const int m0 = (warp >> 1) * 16;
    const int n0 = (warp & 1) * 48;
    const int gid = lane >> 2, tig = lane & 3;
    float d[6][4];
    #pragma unroll
    for (int i = 0; i < 6; i++) { d[i][0] = d[i][1] = d[i][2] = d[i][3] = 0.f; }
    #pragma unroll
    for (int kc = 0; kc < 12; kc++) {
        const int kp = kc * 8 + tig;
        const float* Xb = (kc < 6) ? Sa : Sb;
        const int cb = (kc < 6) ? 0 : -96;
        const float* Xr0 = Xb + (m0 + gid) * ST + cb;
        const float* Xr1 = Xb + (m0 + gid + 8) * ST + cb;
        float2 p00 = *reinterpret_cast<const float2*>(Xr0 + 2 * kp);
        float2 p10 = *reinterpret_cast<const float2*>(Xr1 + 2 * kp);
        float2 p01 = *reinterpret_cast<const float2*>(Xr0 + 2 * (kp + 4));
        float2 p11 = *reinterpret_cast<const float2*>(Xr1 + 2 * (kp + 4));
        uint32_t a0h = cvtbf2(p00.y, p00.x);
        uint32_t a1h = cvtbf2(p10.y, p10.x);
        uint32_t a2h = cvtbf2(p01.y, p01.x);
        uint32_t a3h = cvtbf2(p11.y, p11.x);
        uint32_t a0l = cvtbf2(p00.y - bhi2f(a0h), p00.x - blo2f(a0h));
        uint32_t a1l = cvtbf2(p10.y - bhi2f(a1h), p10.x - blo2f(a1h));
        uint32_t a2l = cvtbf2(p01.y - bhi2f(a2h), p01.x - blo2f(a2h));
        uint32_t a3l = cvtbf2(p11.y - bhi2f(a3h), p11.x - blo2f(a3h));
        const uint32_t* Bh0 = g_whi + WPROJ_OFF + kp * 96 + n0 + gid;
        const uint32_t* Bh1 = g_whi + WPROJ_OFF + (kp + 4) * 96 + n0 + gid;
        const uint32_t* Bl0 = g_wlo + WPROJ_OFF + kp * 96 + n0 + gid;
        const uint32_t* Bl1 = g_wlo + WPROJ_OFF + (kp + 4) * 96 + n0 + gid;
        #pragma unroll
        for (int nt = 0; nt < 6; nt++) {
            uint32_t b0h = Bh0[nt * 8], b1h = Bh1[nt * 8];
            uint32_t b0l = Bl0[nt * 8], b1l = Bl1[nt * 8];
            mma16(d[nt], a0h, a1h, a2h, a3h, b0h, b1h);
            mma16(d[nt], a0h, a1h, a2h, a3h, b0l, b1l);
            mma16(d[nt], a0l, a1l, a2l, a3l, b0h, b1h);
        }
    }
    const int r0 = m0 + gid, r1 = m0 + gid + 8;
    #pragma unroll
    for (int nt = 0; nt < 6; nt++) {
        int n = n0 + nt * 8 + tig * 2;
        float bx = bias[n], by = bias[n + 1];
        if (r0 < NTOK) {
            float2 v = make_float2(d[nt][0] + bx, d[nt][1] + by);
            *reinterpret_cast<float2*>(og + r0 * NCH + n) = v;
        }
        if (r1 < NTOK) {
            float2 v = make_float2(d[nt][2] + bx, d[nt][3] + by);
            *reinterpret_cast<float2*>(og + r1 * NCH + n) = v;
        }
    }
}

// ---- depthwise 3x3 conv, 4ch x 5tok per thread (240 active) ----------------
__device__ __forceinline__ void dwconv5(const float* In, const float* __restrict__ Wc,
                                        float* Out, int tid, int mode)
{
    if (tid >= 240) return;
    const int c0 = (tid / 10) * 4, t0 = (tid % 10) * 5;
    u64 wc[9][2];
    #pragma unroll
    for (int s = 0; s < 9; s++) {
        const ulonglong2* wp = reinterpret_cast<const ulonglong2*>(Wc + s * 96 + c0);
        ulonglong2 w = *wp;
        wc[s][0] = w.x; wc[s][1] = w.y;
    }
    #pragma unroll
    for (int tt = 0; tt < 5; tt++) {
        int t = t0 + tt;
        if (t >= NTOK) break;
        int r = t / 7, cc = t % 7;
        u64 a0 = 0ULL, a1 = 0ULL;
        #pragma unroll
        for (int dr = 0; dr < 3; dr++) {
            int rr = r + dr - 1;
            if (rr < 0 || rr > 6) continue;
            #pragma unroll
            for (int dc = 0; dc < 3; dc++) {
                int c2 = cc + dc - 1;
                if (c2 < 0 || c2 > 6) continue;
                const float* vp = In + (rr * 7 + c2) * ST + c0;
                fma2(a0, lds64(vp), wc[dr * 3 + dc][0]);
                fma2(a1, lds64(vp + 2), wc[dr * 3 + dc][1]);
            }
        }
        float2 p0 = unp(a0), p1 = unp(a1);
        float* o = Out + t * ST + c0;
        if (mode == 0) {
            o[0] = 0.5f * p0.x * (1.f + erff(p0.x * 0.70710678118654752f));
            o[1] = 0.5f * p0.y * (1.f + erff(p0.y * 0.70710678118654752f));
            o[2] = 0.5f * p1.x * (1.f + erff(p1.x * 0.70710678118654752f));
            o[3] = 0.5f * p1.y * (1.f + erff(p1.y * 0.70710678118654752f));
        } else {
            o[0] += p0.x; o[1] += p0.y; o[2] += p1.x; o[3] += p1.y;
        }
    }
}

__global__ __launch_bounds__(NTHR, 2) void winattn_kernel(
    const float* __restrict__ x,
    const float* __restrict__ rpb_table,
    const float* __restrict__ bq,  const float* __restrict__ bk,
    const float* __restrict__ bv,  const float* __restrict__ b_ps,
    const float* __restrict__ b_pc,
    const float* __restrict__ conv1, const float* __restrict__ conv2,
    const float* __restrict__ b_proj,
    float* __restrict__ out)
{
    extern __shared__ float sm[];
    float* A   = sm + OFF_A;      // x -> xc
    float* Bb  = sm + OFF_B;      // q -> sp -> ks -> conv1out
    float* Cc  = sm + OFF_C;      // k -> spat
    float* Dd  = sm + OFF_D;      // v (whole kernel)
    float* Ee  = sm + OFF_E;      // attn scratch -> qs -> out_c/spec
    float* RPB = sm + OFF_RPB;
    float* NQ  = sm + OFF_NQ;
    float* NK  = sm + OFF_NK;
    float* CAT = sm + OFF_CAT;

    const int tid  = threadIdx.x;
    const int blk  = blockIdx.x;
    const int warp = tid >> 5, lane = tid & 31;

    {
        const float4* xg4 = reinterpret_cast<const float4*>(x + (size_t)blk * (NTOK * NCH));
        for (int i4 = tid; i4 < NTOK * 24; i4 += NTHR) {
            float4 v = xg4[i4];
            int t = i4 / 24, c = (i4 % 24) * 4;
            float* p = A + t * ST + c;
            p[0] = v.x; p[1] = v.y; p[2] = v.z; p[3] = v.w;
        }
        for (int i = tid; i < 507; i += NTHR) RPB[i] = rpb_table[i];
    }
    __syncthreads();

    // ---- q, k, v projections ----
    gemm_bf16(A, WQ_OFF, bq, Bb, warp, lane);
    __syncthreads();
    gemm_bf16(A, WK_OFF, bk, Cc, warp, lane);
    __syncthreads();
    gemm_bf16(A, WV_OFF, bv, Dd, warp, lane);
    __syncthreads();

    // ---- spatial attention, per head ----
    for (int h = 0; h < NHEADS; h++) {
        const int ch0 = h * HDIM;
        for (int idx = tid; idx < 7 * NTOK; idx += NTHR) {
            int ig = idx / NTOK, j = idx % NTOK;
            int i0 = ig * 7;
            u64 acc[7];
            #pragma unroll
            for (int a = 0; a < 7; a++) acc[a] = 0ULL;
            const float* Kj = Cc + j * ST + ch0;
            const float* Qb = Bb + i0 * ST + ch0;
            #pragma unroll
            for (int d = 0; d < HDIM; d += 2) {
                u64 k2 = lds64(Kj + d);
                #pragma unroll
                for (int a = 0; a < 7; a++)
                    fma2(acc[a], lds64(Qb + a * ST + d), k2);
            }
            int r2 = j / 7, c2 = j % 7;
            #pragma unroll
            for (int a = 0; a < 7; a++) {
                int i = i0 + a;
                int r1 = i / 7, c1 = i % 7;
                int ridx = (r1 - r2 + 6) * 13 + (c1 - c2 + 6);
                Ee[i * AST + j] = hsum(acc[a]) * SCALEF + RPB[ridx * 3 + h];
            }
        }
        __syncthreads();
        for (int r = warp; r < NTOK; r += 8) {
            float* row = Ee + r * AST;
            float e1 = row[lane];
            bool hi = (lane + 32) < NTOK;
            float e2 = hi ? row[lane + 32] : -3.4e38f;
            float m = fmaxf(e1, e2);
            #pragma unroll
            for (int o = 16; o > 0; o >>= 1) m = fmaxf(m, __shfl_xor_sync(0xffffffffu, m, o));
            float p1 = __expf(e1 - m);
            float p2 = hi ? __expf(e2 - m) : 0.f;
            float s = p1 + p2;
            #pragma unroll
            for (int o = 16; o > 0; o >>= 1) s += __shfl_xor_sync(0xffffffffu, s, o);
            float inv = 1.f / s;
            row[lane] = p1 * inv;
            if (hi) row[lane + 32] = p2 * inv;
        }
        __syncthreads();
        if (tid < 224) {
            int dg = tid / 7, tg = tid % 7;
            int t0 = tg * 7;
            float accs[7];
            #pragma unroll
            for (int t = 0; t < 7; t++) accs[t] = 0.f;
            u64 acc[7];
            #pragma unroll
            for (int t = 0; t < 7; t++) acc[t] = 0ULL;
            #pragma unroll 4
            for (int m = 0; m < 48; m += 2) {
                float va = Dd[m * ST + ch0 + dg];
                float vb = Dd[(m + 1) * ST + ch0 + dg];
                u64 v2; asm("mov.b64 %0,{%1,%2};" : "=l"(v2) : "f"(va), "f"(vb));
                #pragma unroll
                for (int t = 0; t < 7; t++)
                    fma2(acc[t], lds64(Ee + (t0 + t) * AST + m), v2);
            }
            {
                float va = Dd[48 * ST + ch0 + dg];
                #pragma unroll
                for (int t = 0; t < 7; t++)
                    accs[t] = Ee[(t0 + t) * AST + 48] * va;
            }
            #pragma unroll
            for (int t = 0; t < 7; t++)
                Bb[(t0 + t) * ST + ch0 + dg] = hsum(acc[t]) + accs[t];
        }
        __syncthreads();
    }

    // ---- spatial_x = sp @ w_ps + b_ps -> C ----
    gemm_bf16(Bb, WPS_OFF, b_ps, Cc, warp, lane);
    __syncthreads();
    gemm_bf16(A, WQSP_OFF, 0, Ee, warp, lane);     // qs -> E
    __syncthreads();
    gemm_bf16(A, WKSP_OFF, 0, Bb, warp, lane);     // ks -> B
    __syncthreads();

    // ---- inverse L2 norms per channel ----
    if (tid < 96) {
        float s = 0.f;
        for (int t = 0; t < NTOK; t++) { float v = Ee[t * ST + tid]; s += v * v; }
        NQ[tid] = rsqrtf(fmaxf(s, 1e-24f));
    } else if (tid < 192) {
        int c = tid - 96;
        float s = 0.f;
        for (int t = 0; t < NTOK; t++) { float v = Bb[t * ST + c]; s += v * v; }
        NK[c] = rsqrtf(fmaxf(s, 1e-24f));
    }
    __syncthreads();

    // ---- cattn raw (ks=B, qs=E) ----
    if (tid < 192) {
        int h = tid / 64, r = tid % 64;
        int d0 = (r / 8) * 4, e0 = (r % 8) * 4;
        int ch = h * HDIM;
        u64 acc[4][2];
        #pragma unroll
        for (int i = 0; i < 4; i++) { acc[i][0] = 0ULL; acc[i][1] = 0ULL; }
        for (int t = 0; t < NTOK; t++) {
            u64 q0 = lds64(Ee + t * ST + ch + e0);
            u64 q1 = lds64(Ee + t * ST + ch + e0 + 2);
            float2 k01 = unp(lds64(Bb + t * ST + ch + d0));
            float2 k23 = unp(lds64(Bb + t * ST + ch + d0 + 2));
            u64 kd0 = dup2(k01.x), kd1 = dup2(k01.y);
            u64 kd2 = dup2(k23.x), kd3 = dup2(k23.y);
            fma2(acc[0][0], kd0, q0); fma2(acc[0][1], kd0, q1);
            fma2(acc[1][0], kd1, q0); fma2(acc[1][1], kd1, q1);
            fma2(acc[2][0], kd2, q0); fma2(acc[2][1], kd2, q1);
            fma2(acc[3][0], kd3, q0); fma2(acc[3][1], kd3, q1);
        }
        #pragma unroll
        for (int i = 0; i < 4; i++) {
            float invk = NK[ch + d0 + i] * SCALEF;
            float2 a0 = unp(acc[i][0]), a1 = unp(acc[i][1]);
            float* o = CAT + h * 1088 + (d0 + i) * CST + e0;
            o[0] = a0.x * invk * NQ[ch + e0 + 0];
            o[1] = a0.y * invk * NQ[ch + e0 + 1];
            o[2] = a1.x * invk * NQ[ch + e0 + 2];
            o[3] = a1.y * invk * NQ[ch + e0 + 3];
        }
    }
    __syncthreads();
    for (int rid = warp; rid < 96; rid += 8) {
        float* row = CAT + (rid >> 5) * 1088 + (rid & 31) * CST;
        float e = row[lane];
        float m = e;
        #pragma unroll
        for (int o = 16; o > 0; o >>= 1) m = fmaxf(m, __shfl_xor_sync(0xffffffffu, m, o));
        float p = __expf(e - m);
        float s = p;
        #pragma unroll
        for (int o = 16; o > 0; o >>= 1) s += __shfl_xor_sync(0xffffffffu, s, o);
        row[lane] = p * (1.f / s);
    }
    __syncthreads();

    // ---- xc = cattn @ v -> A ----
    if (tid < 240) {
        int jg = tid / 10, tg = tid % 10;
        int c0 = jg * 4, t0 = tg * 5;
        int h = c0 / HDIM, d0 = c0 % HDIM, ch = h * HDIM;
        const float* CR = CAT + h * 1088;
        u64 acc[5][4];
        #pragma unroll
        for (int t = 0; t < 5; t++)
            #pragma unroll
            for (int i = 0; i < 4; i++) acc[t][i] = 0ULL;
        #pragma unroll 4
        for (int e = 0; e < HDIM; e += 2) {
            u64 w0 = lds64(CR + (d0 + 0) * CST + e);
            u64 w1 = lds64(CR + (d0 + 1) * CST + e);
            u64 w2 = lds64(CR + (d0 + 2) * CST + e);
            u64 w3 = lds64(CR + (d0 + 3) * CST + e);
            #pragma unroll
            for (int t = 0; t < 5; t++) {
                u64 v2 = lds64(Dd + (t0 + t) * ST + ch + e);
                fma2(acc[t][0], v2, w0);
                fma2(acc[t][1], v2, w1);
                fma2(acc[t][2], v2, w2);
                fma2(acc[t][3], v2, w3);
            }
        }
        #pragma unroll
        for (int t = 0; t < 5; t++) {
            if (t0 + t < NTOK) {
                float* o = A + (t0 + t) * ST + c0;
                o[0] = hsum(acc[t][0]); o[1] = hsum(acc[t][1]);
                o[2] = hsum(acc[t][2]); o[3] = hsum(acc[t][3]);
            }
        }
    }
    __syncthreads();

    // ---- out_c = xc @ w_pc + b_pc -> E ----
    gemm_bf16(A, WPC_OFF, b_pc, Ee, warp, lane);
    __syncthreads();

    // ---- conv1(v) + GELU -> B ----
    dwconv5(Dd, conv1, Bb, tid, 0);
    __syncthreads();

    // ---- conv2(gelu) -> E += ----
    dwconv5(Bb, conv2, Ee, tid, 1);
    __syncthreads();

    // ---- final projection ----
    proj_bf16(Cc, Ee, b_proj, out + (size_t)blk * (NTOK * NCH), warp, lane);
}

extern "C" void kernel_launch(void* const* d_in, const int* in_sizes, int n_in,
                              void* d_out, int out_size)
{
    const float* x      = (const float*)d_in[0];
    const float* rpb    = (const float*)d_in[1];
    const float* wq     = (const float*)d_in[2];
    const float* bq     = (const float*)d_in[3];
    const float* wk     = (const float*)d_in[4];
    const float* bk     = (const float*)d_in[5];
    const float* wv     = (const float*)d_in[6];
    const float* bv     = (const float*)d_in[7];
    const float* w_ps   = (const float*)d_in[8];
    const float* b_ps   = (const float*)d_in[9];
    const float* wq_sp  = (const float*)d_in[10];
    const float* wk_sp  = (const float*)d_in[11];
    const float* w_pc   = (const float*)d_in[12];
    const float* b_pc   = (const float*)d_in[13];
    const float* conv1  = (const float*)d_in[14];
    const float* conv2  = (const float*)d_in[15];
    const float* w_proj = (const float*)d_in[16];
    const float* b_proj = (const float*)d_in[17];
    float* out = (float*)d_out;

    int nwin = in_sizes[0] / (NTOK * NCH);

    prep_weights<<<(WTOT + 255) / 256, 256>>>(wq, wk, wv, w_ps, wq_sp, wk_sp, w_pc, w_proj);

    cudaFuncSetAttribute(winattn_kernel,
                         cudaFuncAttributeMaxDynamicSharedMemorySize, SMEM_BYTES);
    winattn_kernel<<<nwin, NTHR, SMEM_BYTES>>>(
        x, rpb, bq, bk, bv, b_ps, b_pc, conv1, conv2, b_proj, out);
}

// round 8
// speedup vs baseline: 1.8196x; 1.4841x over previous
#include <cuda_runtime.h>
#include <math.h>
#include <stdint.h>

// ---------------------------------------------------------------------------
// WindowAttention fused kernel, round 8:
//  - bf16-split (hi/lo, 3-term) m16n8k16 mma for GEMMs, scores AND attn@V
//  - B weight fragments pre-packed in warp order -> 1 coalesced LDG.128 each
//  - irregular small phases (cattn, xc, convs) stay FFMA2+LDS.64
// 256 threads, ~112KB smem, 2 CTAs/SM.
// ---------------------------------------------------------------------------

#define NTOK   49
#define NCH    96
#define NHEADS 3
#define HDIM   32
#define ST     98
#define AST    50
#define CST    34
#define SCALEF 0.17677669529663687f
#define NTHR   256

#define BUF     (NTOK*ST)
#define OFF_A   0
#define OFF_B   (OFF_A + BUF)
#define OFF_C   (OFF_B + BUF)
#define OFF_D   (OFF_C + BUF)
#define OFF_E   (OFF_D + BUF)
#define OFF_RPB (OFF_E + BUF)
#define OFF_NQ  (OFF_RPB + 508)
#define OFF_NK  (OFF_NQ + 96)
#define OFF_CAT (OFF_NK + 96)
#define SMEM_FLOATS (OFF_CAT + 3264)
#define SMEM_BYTES  (SMEM_FLOATS * 4)     // 111896

// packed B fragments: per gemm 6kc x 12(nh*6+nt) x 32 lanes of uint4
#define FRAG_PER_G 2304
#define PROJ_FBASE (7 * FRAG_PER_G)        // 16128
#define NFRAG      (PROJ_FBASE + 12 * 12 * 32)  // 20736

__device__ uint4 g_wpack[NFRAG];

typedef unsigned long long u64;

__device__ __forceinline__ u64 dup2(float x) {
    u64 r; asm("mov.b64 %0,{%1,%1};" : "=l"(r) : "f"(x)); return r;
}
__device__ __forceinline__ void fma2(u64& d, u64 a, u64 b) {
    asm("fma.rn.f32x2 %0,%1,%2,%0;" : "+l"(d) : "l"(a), "l"(b));
}
__device__ __forceinline__ float2 unp(u64 a) {
    float2 r; asm("mov.b64 {%0,%1},%2;" : "=f"(r.x), "=f"(r.y) : "l"(a)); return r;
}
__device__ __forceinline__ float hsum(u64 a) {
    float2 p = unp(a); return p.x + p.y;
}
__device__ __forceinline__ u64 lds64(const float* p) {
    return *reinterpret_cast<const u64*>(p);
}
__device__ __forceinline__ uint32_t cvtbf2(float h, float l) {
    uint32_t r; asm("cvt.rn.bf16x2.f32 %0, %1, %2;" : "=r"(r) : "f"(h), "f"(l)); return r;
}
__device__ __forceinline__ float blo2f(uint32_t p) { return __uint_as_float(p << 16); }
__device__ __forceinline__ float bhi2f(uint32_t p) { return __uint_as_float(p & 0xFFFF0000u); }

__device__ __forceinline__ void mma16(float d[4],
                                      uint32_t a0, uint32_t a1, uint32_t a2, uint32_t a3,
                                      uint32_t b0, uint32_t b1) {
    asm volatile("mma.sync.aligned.m16n8k16.row.col.f32.bf16.bf16.f32 "
                 "{%0,%1,%2,%3}, {%4,%5,%6,%7}, {%8,%9}, {%0,%1,%2,%3};"
                 : "+f"(d[0]), "+f"(d[1]), "+f"(d[2]), "+f"(d[3])
                 : "r"(a0), "r"(a1), "r"(a2), "r"(a3), "r"(b0), "r"(b1));
}

// split a f32 pair into bf16x2 hi + lo
__device__ __forceinline__ void split2(float2 p, uint32_t& h, uint32_t& l) {
    h = cvtbf2(p.y, p.x);
    l = cvtbf2(p.y - bhi2f(h), p.x - blo2f(h));
}

// ---------------- prologue: pack weight B-fragments in warp order -----------
__global__ void prep_weights(const float* __restrict__ wq, const float* __restrict__ wk,
                             const float* __restrict__ wv, const float* __restrict__ w_ps,
                             const float* __restrict__ wq_sp, const float* __restrict__ wk_sp,
                             const float* __restrict__ w_pc, const float* __restrict__ w_proj)
{
    int idx = blockIdx.x * 256 + threadIdx.x;
    if (idx >= NFRAG) return;
    const float* Wt[8] = {wq, wk, wv, w_ps, wq_sp, wk_sp, w_pc, w_proj};
    int g, r;
    if (idx < PROJ_FBASE) { g = idx / FRAG_PER_G; r = idx % FRAG_PER_G; }
    else                  { g = 7; r = idx - PROJ_FBASE; }
    int kc   = r / 384;
    int rem  = r % 384;
    int slot = rem / 32;      // nh*6 + nt
    int lane = rem % 32;
    int gid = lane >> 2, tig = lane & 3;
    int kp = kc * 8 + tig;
    int n  = (slot / 6) * 48 + (slot % 6) * 8 + gid;
    const float* W = Wt[g];
    float x0 = W[(2 * kp) * 96 + n];
    float x1 = W[(2 * kp + 1) * 96 + n];
    float y0 = W[(2 * kp + 8) * 96 + n];
    float y1 = W[(2 * kp + 9) * 96 + n];
    uint32_t b0h, b0l, b1h, b1l;
    split2(make_float2(x0, x1), b0h, b0l);
    split2(make_float2(y0, y1), b1h, b1l);
    g_wpack[idx] = make_uint4(b0h, b1h, b0l, b1l);
}

// ---- bf16-split GEMM: OUT[49][96](ST) = X[49][96](ST) @ W + bias ----------
__device__ __forceinline__ void gemm_bf16(const float* Xs, int fbase,
                                          const float* __restrict__ bias, float* Os,
                                          int warp, int lane)
{
    const int m0 = (warp >> 1) * 16;
    const int nh = warp & 1;
    const int n0 = nh * 48;
    const int gid = lane >> 2, tig = lane & 3;
    float d[6][4];
    #pragma unroll
    for (int i = 0; i < 6; i++) { d[i][0] = d[i][1] = d[i][2] = d[i][3] = 0.f; }
    const float* Xr0 = Xs + (m0 + gid) * ST;
    const float* Xr1 = Xs + (m0 + gid + 8) * ST;
    #pragma unroll
    for (int kc = 0; kc < 6; kc++) {
        const int kp = kc * 8 + tig;
        uint32_t a0h, a0l, a1h, a1l, a2h, a2l, a3h, a3l;
        split2(*reinterpret_cast<const float2*>(Xr0 + 2 * kp), a0h, a0l);
        split2(*reinterpret_cast<const float2*>(Xr1 + 2 * kp), a1h, a1l);
        split2(*reinterpret_cast<const float2*>(Xr0 + 2 * kp + 8), a2h, a2l);
        split2(*reinterpret_cast<const float2*>(Xr1 + 2 * kp + 8), a3h, a3l);
        const uint4* Bf = g_wpack + fbase + (kc * 12 + nh * 6) * 32 + lane;
        #pragma unroll
        for (int nt = 0; nt < 6; nt++) {
            uint4 w = Bf[nt * 32];
            mma16(d[nt], a0h, a1h, a2h, a3h, w.x, w.y);
            mma16(d[nt], a0h, a1h, a2h, a3h, w.z, w.w);
            mma16(d[nt], a0l, a1l, a2l, a3l, w.x, w.y);
        }
    }
    const int r0 = m0 + gid, r1 = m0 + gid + 8;
    #pragma unroll
    for (int nt = 0; nt < 6; nt++) {
        int n = n0 + nt * 8 + tig * 2;
        float bx = 0.f, by = 0.f;
        if (bias) { bx = bias[n]; by = bias[n + 1]; }
        if (r0 < NTOK) { float* o = Os + r0 * ST + n; o[0] = d[nt][0] + bx; o[1] = d[nt][1] + by; }
        if (r1 < NTOK) { float* o = Os + r1 * ST + n; o[0] = d[nt][2] + bx; o[1] = d[nt][3] + by; }
    }
}

// ---- final projection: out = [Sa|Sb](K=192) @ w_proj + b_proj --------------
__device__ __forceinline__ void proj_bf16(const float* Sa, const float* Sb,
                                          const float* __restrict__ bias,
                                          float* __restrict__ og, int warp, int lane)
{
    const int m0 = (warp >> 1) * 16;
    const int nh = warp & 1;
    const int n0 = nh * 48;
    const int gid = lane >> 2, tig = lane & 3;
    float d[6][4];
    #pragma unroll
    for (int i = 0; i < 6; i++) { d[i][0] = d[i][1] = d[i][2] = d[i][3] = 0.f; }
    #pragma unroll
    for (int kc = 0; kc < 12; kc++) {
        const int kp = (kc % 6) * 8 + tig;
        const float* Xb = (kc < 6) ? Sa : Sb;
        const float* Xr0 = Xb + (m0 + gid) * ST;
        const float* Xr1 = Xb + (m0 + gid + 8) * ST;
        uint32_t a0h, a0l, a1h, a1l, a2h, a2l, a3h, a3l;
        split2(*reinterpret_cast<const float2*>(Xr0 + 2 * kp), a0h, a0l);
        split2(*reinterpret_cast<const float2*>(Xr1 + 2 * kp), a1h, a1l);
        split2(*reinterpret_cast<const float2*>(Xr0 + 2 * kp + 8), a2h, a2l);
        split2(*reinterpret_cast<const float2*>(Xr1 + 2 * kp + 8), a3h, a3l);
        const uint4* Bf = g_wpack + PROJ_FBASE + (kc * 12 + nh * 6) * 32 + lane;
        #pragma unroll
        for (int nt = 0; nt < 6; nt++) {
            uint4 w = Bf[nt * 32];
            mma16(d[nt], a0h, a1h, a2h, a3h, w.x, w.y);
            mma16(d[nt], a0h, a1h, a2h, a3h, w.z, w.w);
            mma16(d[nt], a0l, a1l, a2l, a3l, w.x, w.y);
        }
    }
    const int r0 = m0 + gid, r1 = m0 + gid + 8;
    #pragma unroll
    for (int nt = 0; nt < 6; nt++) {
        int n = n0 + nt * 8 + tig * 2;
        float bx = bias[n], by = bias[n + 1];
        if (r0 < NTOK) {
            float2 v = make_float2(d[nt][0] + bx, d[nt][1] + by);
            *reinterpret_cast<float2*>(og + r0 * NCH + n) = v;
        }
        if (r1 < NTOK) {
            float2 v = make_float2(d[nt][2] + bx, d[nt][3] + by);
            *reinterpret_cast<float2*>(og + r1 * NCH + n) = v;
        }
    }
}

// ---- scores via MMA: SCR[i][j] = scale*q_i.k_j + rpb, one head --------------
__device__ __forceinline__ void scores_mma(const float* Q, const float* K,
                                           float* SCR, const float* RPB,
                                           int h, int warp, int lane)
{
    const int ch0 = h * HDIM;
    const int m0 = (warp >> 1) * 16;
    const int n0 = (warp & 1) * 32;
    const int gid = lane >> 2, tig = lane & 3;
    float d[4][4];
    #pragma unroll
    for (int i = 0; i < 4; i++) { d[i][0] = d[i][1] = d[i][2] = d[i][3] = 0.f; }
    const float* Qr0 = Q + (m0 + gid) * ST + ch0;
    const float* Qr1 = Qr0 + 8 * ST;
    #pragma unroll
    for (int kc = 0; kc < 2; kc++) {
        const int kp = kc * 8 + tig;
        uint32_t a0h, a0l, a1h, a1l, a2h, a2l, a3h, a3l;
        split2(*reinterpret_cast<const float2*>(Qr0 + 2 * kp), a0h, a0l);
        split2(*reinterpret_cast<const float2*>(Qr1 + 2 * kp), a1h, a1l);
        split2(*reinterpret_cast<const float2*>(Qr0 + 2 * kp + 8), a2h, a2l);
        split2(*reinterpret_cast<const float2*>(Qr1 + 2 * kp + 8), a3h, a3l);
        #pragma unroll
        for (int nt = 0; nt < 4; nt++) {
            const float* Kr = K + (n0 + nt * 8 + gid) * ST + ch0;
            uint32_t b0h, b0l, b1h, b1l;
            split2(*reinterpret_cast<const float2*>(Kr + 2 * kp), b0h, b0l);
            split2(*reinterpret_cast<const float2*>(Kr + 2 * kp + 8), b1h, b1l);
            mma16(d[nt], a0h, a1h, a2h, a3h, b0h, b1h);
            mma16(d[nt], a0h, a1h, a2h, a3h, b0l, b1l);
            mma16(d[nt], a0l, a1l, a2l, a3l, b0h, b1h);
        }
    }
    const int r0 = m0 + gid, r1 = r0 + 8;
    const int i0r = r0 / 7, i0c = r0 % 7;
    const int i1r = r1 / 7, i1c = r1 % 7;
    #pragma unroll
    for (int nt = 0; nt < 4; nt++) {
        #pragma unroll
        for (int c = 0; c < 2; c++) {
            int j = n0 + nt * 8 + tig * 2 + c;
            if (j < NTOK) {
                int jr = j / 7, jc = j % 7;
                if (r0 < NTOK)
                    SCR[r0 * AST + j] = d[nt][c] * SCALEF
                        + RPB[((i0r - jr + 6) * 13 + (i0c - jc + 6)) * 3 + h];
                if (r1 < NTOK)
                    SCR[r1 * AST + j] = d[nt][2 + c] * SCALEF
                        + RPB[((i1r - jr + 6) * 13 + (i1c - jc + 6)) * 3 + h];
            }
        }
    }
}

// ---- attn@V via MMA: O[i][d] = sum_j P[i][j] V[j][d], one head --------------
// K padded 49->64: SCR col 49 zeroed by softmax; k>=50 A-fragments zeroed.
__device__ __forceinline__ void attnv_mma(const float* SCR, const float* V,
                                          float* O, int h, int warp, int lane)
{
    const int ch0 = h * HDIM;
    const int m0 = (warp >> 1) * 16;
    const int n0 = (warp & 1) * 16;
    const int gid = lane >> 2, tig = lane & 3;
    float d[2][4];
    #pragma unroll
    for (int i = 0; i < 2; i++) { d[i][0] = d[i][1] = d[i][2] = d[i][3] = 0.f; }
    const float* Pr0 = SCR + (m0 + gid) * AST;
    const float* Pr1 = Pr0 + 8 * AST;
    #pragma unroll
    for (int kc = 0; kc < 4; kc++) {
        const int k0 = 2 * (kc * 8 + tig);
        const int k2 = k0 + 8;
        uint32_t a0h = 0, a0l = 0, a1h = 0, a1l = 0;
        uint32_t a2h = 0, a2l = 0, a3h = 0, a3l = 0;
        if (k0 <= 48) {
            split2(*reinterpret_cast<const float2*>(Pr0 + k0), a0h, a0l);
            split2(*reinterpret_cast<const float2*>(Pr1 + k0), a1h, a1l);
        }
        if (k2 <= 48) {
            split2(*reinterpret_cast<const float2*>(Pr0 + k2), a2h, a2l);
            split2(*reinterpret_cast<const float2*>(Pr1 + k2), a3h, a3l);
        }
        #pragma unroll
        for (int nt = 0; nt < 2; nt++) {
            const int n = ch0 + n0 + nt * 8 + gid;
            uint32_t b0h, b0l, b1h, b1l;
            split2(make_float2(V[k0 * ST + n], V[(k0 + 1) * ST + n]), b0h, b0l);
            split2(make_float2(V[k2 * ST + n], V[(k2 + 1) * ST + n]), b1h, b1l);
            mma16(d[nt], a0h, a1h, a2h, a3h, b0h, b1h);
            mma16(d[nt], a0h, a1h, a2h, a3h, b0l, b1l);
            mma16(d[nt], a0l, a1l, a2l, a3l, b0h, b1h);
        }
    }
    const int r0 = m0 + gid, r1 = r0 + 8;
    #pragma unroll
    for (int nt = 0; nt < 2; nt++) {
        int n = ch0 + n0 + nt * 8 + tig * 2;
        if (r0 < NTOK)
            *reinterpret_cast<float2*>(O + r0 * ST + n) = make_float2(d[nt][0], d[nt][1]);
        if (r1 < NTOK)
            *reinterpret_cast<float2*>(O + r1 * ST + n) = make_float2(d[nt][2], d[nt][3]);
    }
}

// ---- depthwise 3x3 conv, 4ch x 5tok per thread (240 active) ----------------
__device__ __forceinline__ void dwconv5(const float* In, const float* __restrict__ Wc,
                                        float* Out, int tid, int mode)
{
    if (tid >= 240) return;
    const int c0 = (tid / 10) * 4, t0 = (tid % 10) * 5;
    u64 wc[9][2];
    #pragma unroll
    for (int s = 0; s < 9; s++) {
        const ulonglong2* wp = reinterpret_cast<const ulonglong2*>(Wc + s * 96 + c0);
        ulonglong2 w = *wp;
        wc[s][0] = w.x; wc[s][1] = w.y;
    }
    #pragma unroll
    for (int tt = 0; tt < 5; tt++) {
        int t = t0 + tt;
        if (t >= NTOK) break;
        int r = t / 7, cc = t % 7;
        u64 a0 = 0ULL, a1 = 0ULL;
        #pragma unroll
        for (int dr = 0; dr < 3; dr++) {
            int rr = r + dr - 1;
            if (rr < 0 || rr > 6) continue;
            #pragma unroll
            for (int dc = 0; dc < 3; dc++) {
                int c2 = cc + dc - 1;
                if (c2 < 0 || c2 > 6) continue;
                const float* vp = In + (rr * 7 + c2) * ST + c0;
                fma2(a0, lds64(vp), wc[dr * 3 + dc][0]);
                fma2(a1, lds64(vp + 2), wc[dr * 3 + dc][1]);
            }
        }
        float2 p0 = unp(a0), p1 = unp(a1);
        float* o = Out + t * ST + c0;
        if (mode == 0) {
            o[0] = 0.5f * p0.x * (1.f + erff(p0.x * 0.70710678118654752f));
            o[1] = 0.5f * p0.y * (1.f + erff(p0.y * 0.70710678118654752f));
            o[2] = 0.5f * p1.x * (1.f + erff(p1.x * 0.70710678118654752f));
            o[3] = 0.5f * p1.y * (1.f + erff(p1.y * 0.70710678118654752f));
        } else {
            o[0] += p0.x; o[1] += p0.y; o[2] += p1.x; o[3] += p1.y;
        }
    }
}

__global__ __launch_bounds__(NTHR, 2) void winattn_kernel(
    const float* __restrict__ x,
    const float* __restrict__ rpb_table,
    const float* __restrict__ bq,  const float* __restrict__ bk,
    const float* __restrict__ bv,  const float* __restrict__ b_ps,
    const float* __restrict__ b_pc,
    const float* __restrict__ conv1, const float* __restrict__ conv2,
    const float* __restrict__ b_proj,
    float* __restrict__ out)
{
    extern __shared__ float sm[];
    float* A   = sm + OFF_A;      // x -> xc
    float* Bb  = sm + OFF_B;      // q -> sp -> ks -> conv1out
    float* Cc  = sm + OFF_C;      // k -> spat
    float* Dd  = sm + OFF_D;      // v (whole kernel)
    float* Ee  = sm + OFF_E;      // attn scratch -> qs -> out_c/spec
    float* RPB = sm + OFF_RPB;
    float* NQ  = sm + OFF_NQ;
    float* NK  = sm + OFF_NK;
    float* CAT = sm + OFF_CAT;

    const int tid  = threadIdx.x;
    const int blk  = blockIdx.x;
    const int warp = tid >> 5, lane = tid & 31;

    {
        const float4* xg4 = reinterpret_cast<const float4*>(x + (size_t)blk * (NTOK * NCH));
        for (int i4 = tid; i4 < NTOK * 24; i4 += NTHR) {
            float4 v = xg4[i4];
            int t = i4 / 24, c = (i4 % 24) * 4;
            float* p = A + t * ST + c;
            p[0] = v.x; p[1] = v.y; p[2] = v.z; p[3] = v.w;
        }
        for (int i = tid; i < 507; i += NTHR) RPB[i] = rpb_table[i];
    }
    __syncthreads();

    // ---- q, k, v projections ----
    gemm_bf16(A, 0 * FRAG_PER_G, bq, Bb, warp, lane);
    __syncthreads();
    gemm_bf16(A, 1 * FRAG_PER_G, bk, Cc, warp, lane);
    __syncthreads();
    gemm_bf16(A, 2 * FRAG_PER_G, bv, Dd, warp, lane);
    __syncthreads();

    // ---- spatial attention, per head (all-MMA) ----
    for (int h = 0; h < NHEADS; h++) {
        scores_mma(Bb, Cc, Ee, RPB, h, warp, lane);
        __syncthreads();
        for (int r = warp; r < NTOK; r += 8) {
            float* row = Ee + r * AST;
            float e1 = row[lane];
            bool hi = (lane + 32) < NTOK;
            float e2 = hi ? row[lane + 32] : -3.4e38f;
            float m = fmaxf(e1, e2);
            #pragma unroll
            for (int o = 16; o > 0; o >>= 1) m = fmaxf(m, __shfl_xor_sync(0xffffffffu, m, o));
            float p1 = __expf(e1 - m);
            float p2 = hi ? __expf(e2 - m) : 0.f;
            float s = p1 + p2;
            #pragma unroll
            for (int o = 16; o > 0; o >>= 1) s += __shfl_xor_sync(0xffffffffu, s, o);
            float inv = 1.f / s;
            row[lane] = p1 * inv;
            if (hi) row[lane + 32] = p2 * inv;
            if (lane == 0) row[NTOK] = 0.f;   // zero pad col 49 for attn@V k-padding
        }
        __syncthreads();
        attnv_mma(Ee, Dd, Bb, h, warp, lane);
        __syncthreads();
    }

    // ---- spatial_x = sp @ w_ps + b_ps -> C ----
    gemm_bf16(Bb, 3 * FRAG_PER_G, b_ps, Cc, warp, lane);
    __syncthreads();
    gemm_bf16(A, 4 * FRAG_PER_G, 0, Ee, warp, lane);     // qs -> E
    __syncthreads();
    gemm_bf16(A, 5 * FRAG_PER_G, 0, Bb, warp, lane);     // ks -> B
    __syncthreads();

    // ---- inverse L2 norms per channel ----
    if (tid < 96) {
        float s = 0.f;
        for (int t = 0; t < NTOK; t++) { float v = Ee[t * ST + tid]; s += v * v; }
        NQ[tid] = rsqrtf(fmaxf(s, 1e-24f));
    } else if (tid < 192) {
        int c = tid - 96;
        float s = 0.f;
        for (int t = 0; t < NTOK; t++) { float v = Bb[t * ST + c]; s += v * v; }
        NK[c] = rsqrtf(fmaxf(s, 1e-24f));
    }
    __syncthreads();

    // ---- cattn raw (ks=B, qs=E) ----
    if (tid < 192) {
        int h = tid / 64, r = tid % 64;
        int d0 = (r / 8) * 4, e0 = (r % 8) * 4;
        int ch = h * HDIM;
        u64 acc[4][2];
        #pragma unroll
        for (int i = 0; i < 4; i++) { acc[i][0] = 0ULL; acc[i][1] = 0ULL; }
        for (int t = 0; t < NTOK; t++) {
            u64 q0 = lds64(Ee + t * ST + ch + e0);
            u64 q1 = lds64(Ee + t * ST + ch + e0 + 2);
            float2 k01 = unp(lds64(Bb + t * ST + ch + d0));
            float2 k23 = unp(lds64(Bb + t * ST + ch + d0 + 2));
            u64 kd0 = dup2(k01.x), kd1 = dup2(k01.y);
            u64 kd2 = dup2(k23.x), kd3 = dup2(k23.y);
            fma2(acc[0][0], kd0, q0); fma2(acc[0][1], kd0, q1);
            fma2(acc[1][0], kd1, q0); fma2(acc[1][1], kd1, q1);
            fma2(acc[2][0], kd2, q0); fma2(acc[2][1], kd2, q1);
            fma2(acc[3][0], kd3, q0); fma2(acc[3][1], kd3, q1);
        }
        #pragma unroll
        for (int i = 0; i < 4; i++) {
            float invk = NK[ch + d0 + i] * SCALEF;
            float2 a0 = unp(acc[i][0]), a1 = unp(acc[i][1]);
            float* o = CAT + h * 1088 + (d0 + i) * CST + e0;
            o[0] = a0.x * invk * NQ[ch + e0 + 0];
            o[1] = a0.y * invk * NQ[ch + e0 + 1];
            o[2] = a1.x * invk * NQ[ch + e0 + 2];
            o[3] = a1.y * invk * NQ[ch + e0 + 3];
        }
    }
    __syncthreads();
    for (int rid = warp; rid < 96; rid += 8) {
        float* row = CAT + (rid >> 5) * 1088 + (rid & 31) * CST;
        float e = row[lane];
        float m = e;
        #pragma unroll
        for (int o = 16; o > 0; o >>= 1) m = fmaxf(m, __shfl_xor_sync(0xffffffffu, m, o));
        float p = __expf(e - m);
        float s = p;
        #pragma unroll
        for (int o = 16; o > 0; o >>= 1) s += __shfl_xor_sync(0xffffffffu, s, o);
        row[lane] = p * (1.f / s);
    }
    __syncthreads();

    // ---- xc = cattn @ v -> A ----
    if (tid < 240) {
        int jg = tid / 10, tg = tid % 10;
        int c0 = jg * 4, t0 = tg * 5;
        int h = c0 / HDIM, d0 = c0 % HDIM, ch = h * HDIM;
        const float* CR = CAT + h * 1088;
        u64 acc[5][4];
        #pragma unroll
        for (int t = 0; t < 5; t++)
            #pragma unroll
            for (int i = 0; i < 4; i++) acc[t][i] = 0ULL;
        #pragma unroll 4
        for (int e = 0; e < HDIM; e += 2) {
            u64 w0 = lds64(CR + (d0 + 0) * CST + e);
            u64 w1 = lds64(CR + (d0 + 1) * CST + e);
            u64 w2 = lds64(CR + (d0 + 2) * CST + e);
            u64 w3 = lds64(CR + (d0 + 3) * CST + e);
            #pragma unroll
            for (int t = 0; t < 5; t++) {
                u64 v2 = lds64(Dd + (t0 + t) * ST + ch + e);
                fma2(acc[t][0], v2, w0);
                fma2(acc[t][1], v2, w1);
                fma2(acc[t][2], v2, w2);
                fma2(acc[t][3], v2, w3);
            }
        }
        #pragma unroll
        for (int t = 0; t < 5; t++) {
            if (t0 + t < NTOK) {
                float* o = A + (t0 + t) * ST + c0;
                o[0] = hsum(acc[t][0]); o[1] = hsum(acc[t][1]);
                o[2] = hsum(acc[t][2]); o[3] = hsum(acc[t][3]);
            }
        }
    }
    __syncthreads();

    // ---- out_c = xc @ w_pc + b_pc -> E ----
    gemm_bf16(A, 6 * FRAG_PER_G, b_pc, Ee, warp, lane);
    __syncthreads();

    // ---- conv1(v) + GELU -> B ----
    dwconv5(Dd, conv1, Bb, tid, 0);
    __syncthreads();

    // ---- conv2(gelu) -> E += ----
    dwconv5(Bb, conv2, Ee, tid, 1);
    __syncthreads();

    // ---- final projection ----
    proj_bf16(Cc, Ee, b_proj, out + (size_t)blk * (NTOK * NCH), warp, lane);
}

extern "C" void kernel_launch(void* const* d_in, const int* in_sizes, int n_in,
                              void* d_out, int out_size)
{
    const float* x      = (const float*)d_in[0];
    const float* rpb    = (const float*)d_in[1];
    const float* wq     = (const float*)d_in[2];
    const float* bq     = (const float*)d_in[3];
    const float* wk     = (const float*)d_in[4];
    const float* bk     = (const float*)d_in[5];
    const float* wv     = (const float*)d_in[6];
    const float* bv     = (const float*)d_in[7];
    const float* w_ps   = (const float*)d_in[8];
    const float* b_ps   = (const float*)d_in[9];
    const float* wq_sp  = (const float*)d_in[10];
    const float* wk_sp  = (const float*)d_in[11];
    const float* w_pc   = (const float*)d_in[12];
    const float* b_pc   = (const float*)d_in[13];
    const float* conv1  = (const float*)d_in[14];
    const float* conv2  = (const float*)d_in[15];
    const float* w_proj = (const float*)d_in[16];
    const float* b_proj = (const float*)d_in[17];
    float* out = (float*)d_out;

    int nwin = in_sizes[0] / (NTOK * NCH);

    prep_weights<<<(NFRAG + 255) / 256, 256>>>(wq, wk, wv, w_ps, wq_sp, wk_sp, w_pc, w_proj);

    cudaFuncSetAttribute(winattn_kernel,
                         cudaFuncAttributeMaxDynamicSharedMemorySize, SMEM_BYTES);
    winattn_kernel<<<nwin, NTHR, SMEM_BYTES>>>(
        x, rpb, bq, bk, bv, b_ps, b_pc, conv1, conv2, b_proj, out);
}

// round 9
// speedup vs baseline: 2.0660x; 1.1354x over previous
#include <cuda_runtime.h>
#include <math.h>
#include <stdint.h>

// ---------------------------------------------------------------------------
// WindowAttention fused kernel, round 9: R8 + ST=100 (2-way max bank conflicts
// on MMA operand LDS, was 4-way) + merged independent phases (-4 barriers).
// ---------------------------------------------------------------------------

#define NTOK   49
#define NCH    96
#define NHEADS 3
#define HDIM   32
#define ST     100
#define AST    50
#define CST    34
#define SCALEF 0.17677669529663687f
#define NTHR   256

#define BUF     (NTOK*ST)                  // 4900
#define OFF_A   0
#define OFF_B   (OFF_A + BUF)
#define OFF_C   (OFF_B + BUF)
#define OFF_D   (OFF_C + BUF)
#define OFF_E   (OFF_D + BUF)
#define OFF_RPB (OFF_E + BUF)
#define OFF_NQ  (OFF_RPB + 508)
#define OFF_NK  (OFF_NQ + 96)
#define OFF_CAT (OFF_NK + 96)
#define SMEM_FLOATS (OFF_CAT + 3264)
#define SMEM_BYTES  (SMEM_FLOATS * 4)      // 113856

#define FRAG_PER_G 2304
#define PROJ_FBASE (7 * FRAG_PER_G)
#define NFRAG      (PROJ_FBASE + 12 * 12 * 32)

__device__ uint4 g_wpack[NFRAG];

typedef unsigned long long u64;

__device__ __forceinline__ u64 dup2(float x) {
    u64 r; asm("mov.b64 %0,{%1,%1};" : "=l"(r) : "f"(x)); return r;
}
__device__ __forceinline__ void fma2(u64& d, u64 a, u64 b) {
    asm("fma.rn.f32x2 %0,%1,%2,%0;" : "+l"(d) : "l"(a), "l"(b));
}
__device__ __forceinline__ float2 unp(u64 a) {
    float2 r; asm("mov.b64 {%0,%1},%2;" : "=f"(r.x), "=f"(r.y) : "l"(a)); return r;
}
__device__ __forceinline__ float hsum(u64 a) {
    float2 p = unp(a); return p.x + p.y;
}
__device__ __forceinline__ u64 lds64(const float* p) {
    return *reinterpret_cast<const u64*>(p);
}
__device__ __forceinline__ uint32_t cvtbf2(float h, float l) {
    uint32_t r; asm("cvt.rn.bf16x2.f32 %0, %1, %2;" : "=r"(r) : "f"(h), "f"(l)); return r;
}
__device__ __forceinline__ float blo2f(uint32_t p) { return __uint_as_float(p << 16); }
__device__ __forceinline__ float bhi2f(uint32_t p) { return __uint_as_float(p & 0xFFFF0000u); }

__device__ __forceinline__ void mma16(float d[4],
                                      uint32_t a0, uint32_t a1, uint32_t a2, uint32_t a3,
                                      uint32_t b0, uint32_t b1) {
    asm volatile("mma.sync.aligned.m16n8k16.row.col.f32.bf16.bf16.f32 "
                 "{%0,%1,%2,%3}, {%4,%5,%6,%7}, {%8,%9}, {%0,%1,%2,%3};"
                 : "+f"(d[0]), "+f"(d[1]), "+f"(d[2]), "+f"(d[3])
                 : "r"(a0), "r"(a1), "r"(a2), "r"(a3), "r"(b0), "r"(b1));
}

__device__ __forceinline__ void split2(float2 p, uint32_t& h, uint32_t& l) {
    h = cvtbf2(p.y, p.x);
    l = cvtbf2(p.y - bhi2f(h), p.x - blo2f(h));
}

// ---------------- prologue: pack weight B-fragments in warp order -----------
__global__ void prep_weights(const float* __restrict__ wq, const float* __restrict__ wk,
                             const float* __restrict__ wv, const float* __restrict__ w_ps,
                             const float* __restrict__ wq_sp, const float* __restrict__ wk_sp,
                             const float* __restrict__ w_pc, const float* __restrict__ w_proj)
{
    int idx = blockIdx.x * 256 + threadIdx.x;
    if (idx >= NFRAG) return;
    const float* Wt[8] = {wq, wk, wv, w_ps, wq_sp, wk_sp, w_pc, w_proj};
    int g, r;
    if (idx < PROJ_FBASE) { g = idx / FRAG_PER_G; r = idx % FRAG_PER_G; }
    else                  { g = 7; r = idx - PROJ_FBASE; }
    int kc   = r / 384;
    int rem  = r % 384;
    int slot = rem / 32;
    int lane = rem % 32;
    int gid = lane >> 2, tig = lane & 3;
    int kp = kc * 8 + tig;
    int n  = (slot / 6) * 48 + (slot % 6) * 8 + gid;
    const float* W = Wt[g];
    float x0 = W[(2 * kp) * 96 + n];
    float x1 = W[(2 * kp + 1) * 96 + n];
    float y0 = W[(2 * kp + 8) * 96 + n];
    float y1 = W[(2 * kp + 9) * 96 + n];
    uint32_t b0h, b0l, b1h, b1l;
    split2(make_float2(x0, x1), b0h, b0l);
    split2(make_float2(y0, y1), b1h, b1l);
    g_wpack[idx] = make_uint4(b0h, b1h, b0l, b1l);
}

// ---- bf16-split GEMM: OUT[49][96](ST) = X[49][96](ST) @ W + bias ----------
__device__ __forceinline__ void gemm_bf16(const float* Xs, int fbase,
                                          const float* __restrict__ bias, float* Os,
                                          int warp, int lane)
{
    const int m0 = (warp >> 1) * 16;
    const int nh = warp & 1;
    const int n0 = nh * 48;
    const int gid = lane >> 2, tig = lane & 3;
    float d[6][4];
    #pragma unroll
    for (int i = 0; i < 6; i++) { d[i][0] = d[i][1] = d[i][2] = d[i][3] = 0.f; }
    const float* Xr0 = Xs + (m0 + gid) * ST;
    const float* Xr1 = Xs + (m0 + gid + 8) * ST;
    #pragma unroll
    for (int kc = 0; kc < 6; kc++) {
        const int kp = kc * 8 + tig;
        uint32_t a0h, a0l, a1h, a1l, a2h, a2l, a3h, a3l;
        split2(*reinterpret_cast<const float2*>(Xr0 + 2 * kp), a0h, a0l);
        split2(*reinterpret_cast<const float2*>(Xr1 + 2 * kp), a1h, a1l);
        split2(*reinterpret_cast<const float2*>(Xr0 + 2 * kp + 8), a2h, a2l);
        split2(*reinterpret_cast<const float2*>(Xr1 + 2 * kp + 8), a3h, a3l);
        const uint4* Bf = g_wpack + fbase + (kc * 12 + nh * 6) * 32 + lane;
        #pragma unroll
        for (int nt = 0; nt < 6; nt++) {
            uint4 w = Bf[nt * 32];
            mma16(d[nt], a0h, a1h, a2h, a3h, w.x, w.y);
            mma16(d[nt], a0h, a1h, a2h, a3h, w.z, w.w);
            mma16(d[nt], a0l, a1l, a2l, a3l, w.x, w.y);
        }
    }
    const int r0 = m0 + gid, r1 = m0 + gid + 8;
    #pragma unroll
    for (int nt = 0; nt < 6; nt++) {
        int n = n0 + nt * 8 + tig * 2;
        float bx = 0.f, by = 0.f;
        if (bias) { bx = bias[n]; by = bias[n + 1]; }
        if (r0 < NTOK) { float* o = Os + r0 * ST + n; o[0] = d[nt][0] + bx; o[1] = d[nt][1] + by; }
        if (r1 < NTOK) { float* o = Os + r1 * ST + n; o[0] = d[nt][2] + bx; o[1] = d[nt][3] + by; }
    }
}

// ---- final projection: out = [Sa|Sb](K=192) @ w_proj + b_proj --------------
__device__ __forceinline__ void proj_bf16(const float* Sa, const float* Sb,
                                          const float* __restrict__ bias,
                                          float* __restrict__ og, int warp, int lane)
{
    const int m0 = (warp >> 1) * 16;
    const int nh = warp & 1;
    const int n0 = nh * 48;
    const int gid = lane >> 2, tig = lane & 3;
    float d[6][4];
    #pragma unroll
    for (int i = 0; i < 6; i++) { d[i][0] = d[i][1] = d[i][2] = d[i][3] = 0.f; }
    #pragma unroll
    for (int kc = 0; kc < 12; kc++) {
        const int kp = (kc % 6) * 8 + tig;
        const float* Xb = (kc < 6) ? Sa : Sb;
        const float* Xr0 = Xb + (m0 + gid) * ST;
        const float* Xr1 = Xb + (m0 + gid + 8) * ST;
        uint32_t a0h, a0l, a1h, a1l, a2h, a2l, a3h, a3l;
        split2(*reinterpret_cast<const float2*>(Xr0 + 2 * kp), a0h, a0l);
        split2(*reinterpret_cast<const float2*>(Xr1 + 2 * kp), a1h, a1l);
        split2(*reinterpret_cast<const float2*>(Xr0 + 2 * kp + 8), a2h, a2l);
        split2(*reinterpret_cast<const float2*>(Xr1 + 2 * kp + 8), a3h, a3l);
        const uint4* Bf = g_wpack + PROJ_FBASE + (kc * 12 + nh * 6) * 32 + lane;
        #pragma unroll
        for (int nt = 0; nt < 6; nt++) {
            uint4 w = Bf[nt * 32];
            mma16(d[nt], a0h, a1h, a2h, a3h, w.x, w.y);
            mma16(d[nt], a0h, a1h, a2h, a3h, w.z, w.w);
            mma16(d[nt], a0l, a1l, a2l, a3l, w.x, w.y);
        }
    }
    const int r0 = m0 + gid, r1 = m0 + gid + 8;
    #pragma unroll
    for (int nt = 0; nt < 6; nt++) {
        int n = n0 + nt * 8 + tig * 2;
        float bx = bias[n], by = bias[n + 1];
        if (r0 < NTOK) {
            float2 v = make_float2(d[nt][0] + bx, d[nt][1] + by);
            *reinterpret_cast<float2*>(og + r0 * NCH + n) = v;
        }
        if (r1 < NTOK) {
            float2 v = make_float2(d[nt][2] + bx, d[nt][3] + by);
            *reinterpret_cast<float2*>(og + r1 * NCH + n) = v;
        }
    }
}

// ---- scores via MMA ---------------------------------------------------------
__device__ __forceinline__ void scores_mma(const float* Q, const float* K,
                                           float* SCR, const float* RPB,
                                           int h, int warp, int lane)
{
    const int ch0 = h * HDIM;
    const int m0 = (warp >> 1) * 16;
    const int n0 = (warp & 1) * 32;
    const int gid = lane >> 2, tig = lane & 3;
    float d[4][4];
    #pragma unroll
    for (int i = 0; i < 4; i++) { d[i][0] = d[i][1] = d[i][2] = d[i][3] = 0.f; }
    const float* Qr0 = Q + (m0 + gid) * ST + ch0;
    const float* Qr1 = Qr0 + 8 * ST;
    #pragma unroll
    for (int kc = 0; kc < 2; kc++) {
        const int kp = kc * 8 + tig;
        uint32_t a0h, a0l, a1h, a1l, a2h, a2l, a3h, a3l;
        split2(*reinterpret_cast<const float2*>(Qr0 + 2 * kp), a0h, a0l);
        split2(*reinterpret_cast<const float2*>(Qr1 + 2 * kp), a1h, a1l);
        split2(*reinterpret_cast<const float2*>(Qr0 + 2 * kp + 8), a2h, a2l);
        split2(*reinterpret_cast<const float2*>(Qr1 + 2 * kp + 8), a3h, a3l);
        #pragma unroll
        for (int nt = 0; nt < 4; nt++) {
            const float* Kr = K + (n0 + nt * 8 + gid) * ST + ch0;
            uint32_t b0h, b0l, b1h, b1l;
            split2(*reinterpret_cast<const float2*>(Kr + 2 * kp), b0h, b0l);
            split2(*reinterpret_cast<const float2*>(Kr + 2 * kp + 8), b1h, b1l);
            mma16(d[nt], a0h, a1h, a2h, a3h, b0h, b1h);
            mma16(d[nt], a0h, a1h, a2h, a3h, b0l, b1l);
            mma16(d[nt], a0l, a1l, a2l, a3l, b0h, b1h);
        }
    }
    const int r0 = m0 + gid, r1 = r0 + 8;
    const int i0r = r0 / 7, i0c = r0 % 7;
    const int i1r = r1 / 7, i1c = r1 % 7;
    #pragma unroll
    for (int nt = 0; nt < 4; nt++) {
        #pragma unroll
        for (int c = 0; c < 2; c++) {
            int j = n0 + nt * 8 + tig * 2 + c;
            if (j < NTOK) {
                int jr = j / 7, jc = j % 7;
                if (r0 < NTOK)
                    SCR[r0 * AST + j] = d[nt][c] * SCALEF
                        + RPB[((i0r - jr + 6) * 13 + (i0c - jc + 6)) * 3 + h];
                if (r1 < NTOK)
                    SCR[r1 * AST + j] = d[nt][2 + c] * SCALEF
                        + RPB[((i1r - jr + 6) * 13 + (i1c - jc + 6)) * 3 + h];
            }
        }
    }
}

// ---- attn@V via MMA ---------------------------------------------------------
__device__ __forceinline__ void attnv_mma(const float* SCR, const float* V,
                                          float* O, int h, int warp, int lane)
{
    const int ch0 = h * HDIM;
    const int m0 = (warp >> 1) * 16;
    const int n0 = (warp & 1) * 16;
    const int gid = lane >> 2, tig = lane & 3;
    float d[2][4];
    #pragma unroll
    for (int i = 0; i < 2; i++) { d[i][0] = d[i][1] = d[i][2] = d[i][3] = 0.f; }
    const float* Pr0 = SCR + (m0 + gid) * AST;
    const float* Pr1 = Pr0 + 8 * AST;
    #pragma unroll
    for (int kc = 0; kc < 4; kc++) {
        const int k0 = 2 * (kc * 8 + tig);
        const int k2 = k0 + 8;
        uint32_t a0h = 0, a0l = 0, a1h = 0, a1l = 0;
        uint32_t a2h = 0, a2l = 0, a3h = 0, a3l = 0;
        if (k0 <= 48) {
            split2(*reinterpret_cast<const float2*>(Pr0 + k0), a0h, a0l);
            split2(*reinterpret_cast<const float2*>(Pr1 + k0), a1h, a1l);
        }
        if (k2 <= 48) {
            split2(*reinterpret_cast<const float2*>(Pr0 + k2), a2h, a2l);
            split2(*reinterpret_cast<const float2*>(Pr1 + k2), a3h, a3l);
        }
        #pragma unroll
        for (int nt = 0; nt < 2; nt++) {
            const int n = ch0 + n0 + nt * 8 + gid;
            uint32_t b0h, b0l, b1h, b1l;
            split2(make_float2(V[k0 * ST + n], V[(k0 + 1) * ST + n]), b0h, b0l);
            split2(make_float2(V[k2 * ST + n], V[(k2 + 1) * ST + n]), b1h, b1l);
            mma16(d[nt], a0h, a1h, a2h, a3h, b0h, b1h);
            mma16(d[nt], a0h, a1h, a2h, a3h, b0l, b1l);
            mma16(d[nt], a0l, a1l, a2l, a3l, b0h, b1h);
        }
    }
    const int r0 = m0 + gid, r1 = r0 + 8;
    #pragma unroll
    for (int nt = 0; nt < 2; nt++) {
        int n = ch0 + n0 + nt * 8 + tig * 2;
        if (r0 < NTOK)
            *reinterpret_cast<float2*>(O + r0 * ST + n) = make_float2(d[nt][0], d[nt][1]);
        if (r1 < NTOK)
            *reinterpret_cast<float2*>(O + r1 * ST + n) = make_float2(d[nt][2], d[nt][3]);
    }
}

// ---- depthwise 3x3 conv -----------------------------------------------------
__device__ __forceinline__ void dwconv5(const float* In, const float* __restrict__ Wc,
                                        float* Out, int tid, int mode)
{
    if (tid >= 240) return;
    const int c0 = (tid / 10) * 4, t0 = (tid % 10) * 5;
    u64 wc[9][2];
    #pragma unroll
    for (int s = 0; s < 9; s++) {
        const ulonglong2* wp = reinterpret_cast<const ulonglong2*>(Wc + s * 96 + c0);
        ulonglong2 w = *wp;
        wc[s][0] = w.x; wc[s][1] = w.y;
    }
    #pragma unroll
    for (int tt = 0; tt < 5; tt++) {
        int t = t0 + tt;
        if (t >= NTOK) break;
        int r = t / 7, cc = t % 7;
        u64 a0 = 0ULL, a1 = 0ULL;
        #pragma unroll
        for (int dr = 0; dr < 3; dr++) {
            int rr = r + dr - 1;
            if (rr < 0 || rr > 6) continue;
            #pragma unroll
            for (int dc = 0; dc < 3; dc++) {
                int c2 = cc + dc - 1;
                if (c2 < 0 || c2 > 6) continue;
                const float* vp = In + (rr * 7 + c2) * ST + c0;
                fma2(a0, lds64(vp), wc[dr * 3 + dc][0]);
                fma2(a1, lds64(vp + 2), wc[dr * 3 + dc][1]);
            }
        }
        float2 p0 = unp(a0), p1 = unp(a1);
        float* o = Out + t * ST + c0;
        if (mode == 0) {
            o[0] = 0.5f * p0.x * (1.f + erff(p0.x * 0.70710678118654752f));
            o[1] = 0.5f * p0.y * (1.f + erff(p0.y * 0.70710678118654752f));
            o[2] = 0.5f * p1.x * (1.f + erff(p1.x * 0.70710678118654752f));
            o[3] = 0.5f * p1.y * (1.f + erff(p1.y * 0.70710678118654752f));
        } else {
            o[0] += p0.x; o[1] += p0.y; o[2] += p1.x; o[3] += p1.y;
        }
    }
}

__global__ __launch_bounds__(NTHR, 2) void winattn_kernel(
    const float* __restrict__ x,
    const float* __restrict__ rpb_table,
    const float* __restrict__ bq,  const float* __restrict__ bk,
    const float* __restrict__ bv,  const float* __restrict__ b_ps,
    const float* __restrict__ b_pc,
    const float* __restrict__ conv1, const float* __restrict__ conv2,
    const float* __restrict__ b_proj,
    float* __restrict__ out)
{
    extern __shared__ float sm[];
    float* A   = sm + OFF_A;
    float* Bb  = sm + OFF_B;
    float* Cc  = sm + OFF_C;
    float* Dd  = sm + OFF_D;
    float* Ee  = sm + OFF_E;
    float* RPB = sm + OFF_RPB;
    float* NQ  = sm + OFF_NQ;
    float* NK  = sm + OFF_NK;
    float* CAT = sm + OFF_CAT;

    const int tid  = threadIdx.x;
    const int blk  = blockIdx.x;
    const int warp = tid >> 5, lane = tid & 31;

    {
        const float4* xg4 = reinterpret_cast<const float4*>(x + (size_t)blk * (NTOK * NCH));
        for (int i4 = tid; i4 < NTOK * 24; i4 += NTHR) {
            float4 v = xg4[i4];
            int t = i4 / 24, c = (i4 % 24) * 4;
            float* p = A + t * ST + c;
            p[0] = v.x; p[1] = v.y; p[2] = v.z; p[3] = v.w;
        }
        for (int i = tid; i < 507; i += NTHR) RPB[i] = rpb_table[i];
    }
    __syncthreads();

    // ---- q, k, v projections (independent: one barrier) ----
    gemm_bf16(A, 0 * FRAG_PER_G, bq, Bb, warp, lane);
    gemm_bf16(A, 1 * FRAG_PER_G, bk, Cc, warp, lane);
    gemm_bf16(A, 2 * FRAG_PER_G, bv, Dd, warp, lane);
    __syncthreads();

    // ---- spatial attention, per head (all-MMA) ----
    for (int h = 0; h < NHEADS; h++) {
        scores_mma(Bb, Cc, Ee, RPB, h, warp, lane);
        __syncthreads();
        for (int r = warp; r < NTOK; r += 8) {
            float* row = Ee + r * AST;
            float e1 = row[lane];
            bool hi = (lane + 32) < NTOK;
            float e2 = hi ? row[lane + 32] : -3.4e38f;
            float m = fmaxf(e1, e2);
            #pragma unroll
            for (int o = 16; o > 0; o >>= 1) m = fmaxf(m, __shfl_xor_sync(0xffffffffu, m, o));
            float p1 = __expf(e1 - m);
            float p2 = hi ? __expf(e2 - m) : 0.f;
            float s = p1 + p2;
            #pragma unroll
            for (int o = 16; o > 0; o >>= 1) s += __shfl_xor_sync(0xffffffffu, s, o);
            float inv = 1.f / s;
            row[lane] = p1 * inv;
            if (hi) row[lane + 32] = p2 * inv;
            if (lane == 0) row[NTOK] = 0.f;
        }
        __syncthreads();
        attnv_mma(Ee, Dd, Bb, h, warp, lane);
        __syncthreads();
    }

    // ---- {spatial = sp @ w_ps -> C} and {qs = x @ wq_sp -> E} ----
    gemm_bf16(Bb, 3 * FRAG_PER_G, b_ps, Cc, warp, lane);
    gemm_bf16(A, 4 * FRAG_PER_G, 0, Ee, warp, lane);
    __syncthreads();
    // ---- ks = x @ wk_sp -> B ----
    gemm_bf16(A, 5 * FRAG_PER_G, 0, Bb, warp, lane);
    __syncthreads();

    // ---- inverse L2 norms per channel ----
    if (tid < 96) {
        float s = 0.f;
        for (int t = 0; t < NTOK; t++) { float v = Ee[t * ST + tid]; s += v * v; }
        NQ[tid] = rsqrtf(fmaxf(s, 1e-24f));
    } else if (tid < 192) {
        int c = tid - 96;
        float s = 0.f;
        for (int t = 0; t < NTOK; t++) { float v = Bb[t * ST + c]; s += v * v; }
        NK[c] = rsqrtf(fmaxf(s, 1e-24f));
    }
    __syncthreads();

    // ---- cattn raw (ks=B, qs=E) ----
    if (tid < 192) {
        int h = tid / 64, r = tid % 64;
        int d0 = (r / 8) * 4, e0 = (r % 8) * 4;
        int ch = h * HDIM;
        u64 acc[4][2];
        #pragma unroll
        for (int i = 0; i < 4; i++) { acc[i][0] = 0ULL; acc[i][1] = 0ULL; }
        for (int t = 0; t < NTOK; t++) {
            u64 q0 = lds64(Ee + t * ST + ch + e0);
            u64 q1 = lds64(Ee + t * ST + ch + e0 + 2);
            float2 k01 = unp(lds64(Bb + t * ST + ch + d0));
            float2 k23 = unp(lds64(Bb + t * ST + ch + d0 + 2));
            u64 kd0 = dup2(k01.x), kd1 = dup2(k01.y);
            u64 kd2 = dup2(k23.x), kd3 = dup2(k23.y);
            fma2(acc[0][0], kd0, q0); fma2(acc[0][1], kd0, q1);
            fma2(acc[1][0], kd1, q0); fma2(acc[1][1], kd1, q1);
            fma2(acc[2][0], kd2, q0); fma2(acc[2][1], kd2, q1);
            fma2(acc[3][0], kd3, q0); fma2(acc[3][1], kd3, q1);
        }
        #pragma unroll
        for (int i = 0; i < 4; i++) {
            float invk = NK[ch + d0 + i] * SCALEF;
            float2 a0 = unp(acc[i][0]), a1 = unp(acc[i][1]);
            float* o = CAT + h * 1088 + (d0 + i) * CST + e0;
            o[0] = a0.x * invk * NQ[ch + e0 + 0];
            o[1] = a0.y * invk * NQ[ch + e0 + 1];
            o[2] = a1.x * invk * NQ[ch + e0 + 2];
            o[3] = a1.y * invk * NQ[ch + e0 + 3];
        }
    }
    __syncthreads();
    for (int rid = warp; rid < 96; rid += 8) {
        float* row = CAT + (rid >> 5) * 1088 + (rid & 31) * CST;
        float e = row[lane];
        float m = e;
        #pragma unroll
        for (int o = 16; o > 0; o >>= 1) m = fmaxf(m, __shfl_xor_sync(0xffffffffu, m, o));
        float p = __expf(e - m);
        float s = p;
        #pragma unroll
        for (int o = 16; o > 0; o >>= 1) s += __shfl_xor_sync(0xffffffffu, s, o);
        row[lane] = p * (1.f / s);
    }
    __syncthreads();

    // ---- xc = cattn @ v -> A ----
    if (tid < 240) {
        int jg = tid / 10, tg = tid % 10;
        int c0 = jg * 4, t0 = tg * 5;
        int h = c0 / HDIM, d0 = c0 % HDIM, ch = h * HDIM;
        const float* CR = CAT + h * 1088;
        u64 acc[5][4];
        #pragma unroll
        for (int t = 0; t < 5; t++)
            #pragma unroll
            for (int i = 0; i < 4; i++) acc[t][i] = 0ULL;
        #pragma unroll 4
        for (int e = 0; e < HDIM; e += 2) {
            u64 w0 = lds64(CR + (d0 + 0) * CST + e);
            u64 w1 = lds64(CR + (d0 + 1) * CST + e);
            u64 w2 = lds64(CR + (d0 + 2) * CST + e);
            u64 w3 = lds64(CR + (d0 + 3) * CST + e);
            #pragma unroll
            for (int t = 0; t < 5; t++) {
                u64 v2 = lds64(Dd + (t0 + t) * ST + ch + e);
                fma2(acc[t][0], v2, w0);
                fma2(acc[t][1], v2, w1);
                fma2(acc[t][2], v2, w2);
                fma2(acc[t][3], v2, w3);
            }
        }
        #pragma unroll
        for (int t = 0; t < 5; t++) {
            if (t0 + t < NTOK) {
                float* o = A + (t0 + t) * ST + c0;
                o[0] = hsum(acc[t][0]); o[1] = hsum(acc[t][1]);
                o[2] = hsum(acc[t][2]); o[3] = hsum(acc[t][3]);
            }
        }
    }
    __syncthreads();

    // ---- {out_c = xc @ w_pc -> E} and {conv1(v)+GELU -> B} (independent) ----
    gemm_bf16(A, 6 * FRAG_PER_G, b_pc, Ee, warp, lane);
    dwconv5(Dd, conv1, Bb, tid, 0);
    __syncthreads();

    // ---- conv2(gelu) -> E += ----
    dwconv5(Bb, conv2, Ee, tid, 1);
    __syncthreads();

    // ---- final projection ----
    proj_bf16(Cc, Ee, b_proj, out + (size_t)blk * (NTOK * NCH), warp, lane);
}

extern "C" void kernel_launch(void* const* d_in, const int* in_sizes, int n_in,
                              void* d_out, int out_size)
{
    const float* x      = (const float*)d_in[0];
    const float* rpb    = (const float*)d_in[1];
    const float* wq     = (const float*)d_in[2];
    const float* bq     = (const float*)d_in[3];
    const float* wk     = (const float*)d_in[4];
    const float* bk     = (const float*)d_in[5];
    const float* wv     = (const float*)d_in[6];
    const float* bv     = (const float*)d_in[7];
    const float* w_ps   = (const float*)d_in[8];
    const float* b_ps   = (const float*)d_in[9];
    const float* wq_sp  = (const float*)d_in[10];
    const float* wk_sp  = (const float*)d_in[11];
    const float* w_pc   = (const float*)d_in[12];
    const float* b_pc   = (const float*)d_in[13];
    const float* conv1  = (const float*)d_in[14];
    const float* conv2  = (const float*)d_in[15];
    const float* w_proj = (const float*)d_in[16];
    const float* b_proj = (const float*)d_in[17];
    float* out = (float*)d_out;

    int nwin = in_sizes[0] / (NTOK * NCH);

    prep_weights<<<(NFRAG + 255) / 256, 256>>>(wq, wk, wv, w_ps, wq_sp, wk_sp, w_pc, w_proj);

    cudaFuncSetAttribute(winattn_kernel,
                         cudaFuncAttributeMaxDynamicSharedMemorySize, SMEM_BYTES);
    winattn_kernel<<<nwin, NTHR, SMEM_BYTES>>>(
        x, rpb, bq, bk, bv, b_ps, b_pc, conv1, conv2, b_proj, out);
}

// round 10
// speedup vs baseline: 2.1617x; 1.0463x over previous
#include <cuda_runtime.h>
#include <math.h>
#include <stdint.h>

// ---------------------------------------------------------------------------
// WindowAttention fused kernel, round 10: R9 + cattn and xc converted to
// bf16-split MMA (were the two largest scalar L1 consumers, ~580KB/CTA).
// ---------------------------------------------------------------------------

#define NTOK   49
#define NCH    96
#define NHEADS 3
#define HDIM   32
#define ST     100
#define AST    50
#define CST    34
#define SCALEF 0.17677669529663687f
#define NTHR   256

#define BUF     (NTOK*ST)                  // 4900
#define OFF_A   0
#define OFF_B   (OFF_A + BUF)
#define OFF_C   (OFF_B + BUF)
#define OFF_D   (OFF_C + BUF)
#define OFF_E   (OFF_D + BUF)
#define OFF_RPB (OFF_E + BUF)
#define OFF_NQ  (OFF_RPB + 508)
#define OFF_NK  (OFF_NQ + 96)
#define OFF_CAT (OFF_NK + 96)
#define SMEM_FLOATS (OFF_CAT + 3264)
#define SMEM_BYTES  (SMEM_FLOATS * 4)      // 113856

#define FRAG_PER_G 2304
#define PROJ_FBASE (7 * FRAG_PER_G)
#define NFRAG      (PROJ_FBASE + 12 * 12 * 32)

__device__ uint4 g_wpack[NFRAG];

typedef unsigned long long u64;

__device__ __forceinline__ u64 dup2(float x) {
    u64 r; asm("mov.b64 %0,{%1,%1};" : "=l"(r) : "f"(x)); return r;
}
__device__ __forceinline__ void fma2(u64& d, u64 a, u64 b) {
    asm("fma.rn.f32x2 %0,%1,%2,%0;" : "+l"(d) : "l"(a), "l"(b));
}
__device__ __forceinline__ float2 unp(u64 a) {
    float2 r; asm("mov.b64 {%0,%1},%2;" : "=f"(r.x), "=f"(r.y) : "l"(a)); return r;
}
__device__ __forceinline__ u64 lds64(const float* p) {
    return *reinterpret_cast<const u64*>(p);
}
__device__ __forceinline__ uint32_t cvtbf2(float h, float l) {
    uint32_t r; asm("cvt.rn.bf16x2.f32 %0, %1, %2;" : "=r"(r) : "f"(h), "f"(l)); return r;
}
__device__ __forceinline__ float blo2f(uint32_t p) { return __uint_as_float(p << 16); }
__device__ __forceinline__ float bhi2f(uint32_t p) { return __uint_as_float(p & 0xFFFF0000u); }

__device__ __forceinline__ void mma16(float d[4],
                                      uint32_t a0, uint32_t a1, uint32_t a2, uint32_t a3,
                                      uint32_t b0, uint32_t b1) {
    asm volatile("mma.sync.aligned.m16n8k16.row.col.f32.bf16.bf16.f32 "
                 "{%0,%1,%2,%3}, {%4,%5,%6,%7}, {%8,%9}, {%0,%1,%2,%3};"
                 : "+f"(d[0]), "+f"(d[1]), "+f"(d[2]), "+f"(d[3])
                 : "r"(a0), "r"(a1), "r"(a2), "r"(a3), "r"(b0), "r"(b1));
}

__device__ __forceinline__ void split2(float2 p, uint32_t& h, uint32_t& l) {
    h = cvtbf2(p.y, p.x);
    l = cvtbf2(p.y - bhi2f(h), p.x - blo2f(h));
}

// ---------------- prologue: pack weight B-fragments in warp order -----------
__global__ void prep_weights(const float* __restrict__ wq, const float* __restrict__ wk,
                             const float* __restrict__ wv, const float* __restrict__ w_ps,
                             const float* __restrict__ wq_sp, const float* __restrict__ wk_sp,
                             const float* __restrict__ w_pc, const float* __restrict__ w_proj)
{
    int idx = blockIdx.x * 256 + threadIdx.x;
    if (idx >= NFRAG) return;
    const float* Wt[8] = {wq, wk, wv, w_ps, wq_sp, wk_sp, w_pc, w_proj};
    int g, r;
    if (idx < PROJ_FBASE) { g = idx / FRAG_PER_G; r = idx % FRAG_PER_G; }
    else                  { g = 7; r = idx - PROJ_FBASE; }
    int kc   = r / 384;
    int rem  = r % 384;
    int slot = rem / 32;
    int lane = rem % 32;
    int gid = lane >> 2, tig = lane & 3;
    int kp = kc * 8 + tig;
    int n  = (slot / 6) * 48 + (slot % 6) * 8 + gid;
    const float* W = Wt[g];
    float x0 = W[(2 * kp) * 96 + n];
    float x1 = W[(2 * kp + 1) * 96 + n];
    float y0 = W[(2 * kp + 8) * 96 + n];
    float y1 = W[(2 * kp + 9) * 96 + n];
    uint32_t b0h, b0l, b1h, b1l;
    split2(make_float2(x0, x1), b0h, b0l);
    split2(make_float2(y0, y1), b1h, b1l);
    g_wpack[idx] = make_uint4(b0h, b1h, b0l, b1l);
}

// ---- bf16-split GEMM: OUT[49][96](ST) = X[49][96](ST) @ W + bias ----------
__device__ __forceinline__ void gemm_bf16(const float* Xs, int fbase,
                                          const float* __restrict__ bias, float* Os,
                                          int warp, int lane)
{
    const int m0 = (warp >> 1) * 16;
    const int nh = warp & 1;
    const int n0 = nh * 48;
    const int gid = lane >> 2, tig = lane & 3;
    float d[6][4];
    #pragma unroll
    for (int i = 0; i < 6; i++) { d[i][0] = d[i][1] = d[i][2] = d[i][3] = 0.f; }
    const float* Xr0 = Xs + (m0 + gid) * ST;
    const float* Xr1 = Xs + (m0 + gid + 8) * ST;
    #pragma unroll
    for (int kc = 0; kc < 6; kc++) {
        const int kp = kc * 8 + tig;
        uint32_t a0h, a0l, a1h, a1l, a2h, a2l, a3h, a3l;
        split2(*reinterpret_cast<const float2*>(Xr0 + 2 * kp), a0h, a0l);
        split2(*reinterpret_cast<const float2*>(Xr1 + 2 * kp), a1h, a1l);
        split2(*reinterpret_cast<const float2*>(Xr0 + 2 * kp + 8), a2h, a2l);
        split2(*reinterpret_cast<const float2*>(Xr1 + 2 * kp + 8), a3h, a3l);
        const uint4* Bf = g_wpack + fbase + (kc * 12 + nh * 6) * 32 + lane;
        #pragma unroll
        for (int nt = 0; nt < 6; nt++) {
            uint4 w = Bf[nt * 32];
            mma16(d[nt], a0h, a1h, a2h, a3h, w.x, w.y);
            mma16(d[nt], a0h, a1h, a2h, a3h, w.z, w.w);
            mma16(d[nt], a0l, a1l, a2l, a3l, w.x, w.y);
        }
    }
    const int r0 = m0 + gid, r1 = m0 + gid + 8;
    #pragma unroll
    for (int nt = 0; nt < 6; nt++) {
        int n = n0 + nt * 8 + tig * 2;
        float bx = 0.f, by = 0.f;
        if (bias) { bx = bias[n]; by = bias[n + 1]; }
        if (r0 < NTOK) { float* o = Os + r0 * ST + n; o[0] = d[nt][0] + bx; o[1] = d[nt][1] + by; }
        if (r1 < NTOK) { float* o = Os + r1 * ST + n; o[0] = d[nt][2] + bx; o[1] = d[nt][3] + by; }
    }
}

// ---- final projection: out = [Sa|Sb](K=192) @ w_proj + b_proj --------------
__device__ __forceinline__ void proj_bf16(const float* Sa, const float* Sb,
                                          const float* __restrict__ bias,
                                          float* __restrict__ og, int warp, int lane)
{
    const int m0 = (warp >> 1) * 16;
    const int nh = warp & 1;
    const int n0 = nh * 48;
    const int gid = lane >> 2, tig = lane & 3;
    float d[6][4];
    #pragma unroll
    for (int i = 0; i < 6; i++) { d[i][0] = d[i][1] = d[i][2] = d[i][3] = 0.f; }
    #pragma unroll
    for (int kc = 0; kc < 12; kc++) {
        const int kp = (kc % 6) * 8 + tig;
        const float* Xb = (kc < 6) ? Sa : Sb;
        const float* Xr0 = Xb + (m0 + gid) * ST;
        const float* Xr1 = Xb + (m0 + gid + 8) * ST;
        uint32_t a0h, a0l, a1h, a1l, a2h, a2l, a3h, a3l;
        split2(*reinterpret_cast<const float2*>(Xr0 + 2 * kp), a0h, a0l);
        split2(*reinterpret_cast<const float2*>(Xr1 + 2 * kp), a1h, a1l);
        split2(*reinterpret_cast<const float2*>(Xr0 + 2 * kp + 8), a2h, a2l);
        split2(*reinterpret_cast<const float2*>(Xr1 + 2 * kp + 8), a3h, a3l);
        const uint4* Bf = g_wpack + PROJ_FBASE + (kc * 12 + nh * 6) * 32 + lane;
        #pragma unroll
        for (int nt = 0; nt < 6; nt++) {
            uint4 w = Bf[nt * 32];
            mma16(d[nt], a0h, a1h, a2h, a3h, w.x, w.y);
            mma16(d[nt], a0h, a1h, a2h, a3h, w.z, w.w);
            mma16(d[nt], a0l, a1l, a2l, a3l, w.x, w.y);
        }
    }
    const int r0 = m0 + gid, r1 = m0 + gid + 8;
    #pragma unroll
    for (int nt = 0; nt < 6; nt++) {
        int n = n0 + nt * 8 + tig * 2;
        float bx = bias[n], by = bias[n + 1];
        if (r0 < NTOK) {
            float2 v = make_float2(d[nt][0] + bx, d[nt][1] + by);
            *reinterpret_cast<float2*>(og + r0 * NCH + n) = v;
        }
        if (r1 < NTOK) {
            float2 v = make_float2(d[nt][2] + bx, d[nt][3] + by);
            *reinterpret_cast<float2*>(og + r1 * NCH + n) = v;
        }
    }
}

// ---- scores via MMA ---------------------------------------------------------
__device__ __forceinline__ void scores_mma(const float* Q, const float* K,
                                           float* SCR, const float* RPB,
                                           int h, int warp, int lane)
{
    const int ch0 = h * HDIM;
    const int m0 = (warp >> 1) * 16;
    const int n0 = (warp & 1) * 32;
    const int gid = lane >> 2, tig = lane & 3;
    float d[4][4];
    #pragma unroll
    for (int i = 0; i < 4; i++) { d[i][0] = d[i][1] = d[i][2] = d[i][3] = 0.f; }
    const float* Qr0 = Q + (m0 + gid) * ST + ch0;
    const float* Qr1 = Qr0 + 8 * ST;
    #pragma unroll
    for (int kc = 0; kc < 2; kc++) {
        const int kp = kc * 8 + tig;
        uint32_t a0h, a0l, a1h, a1l, a2h, a2l, a3h, a3l;
        split2(*reinterpret_cast<const float2*>(Qr0 + 2 * kp), a0h, a0l);
        split2(*reinterpret_cast<const float2*>(Qr1 + 2 * kp), a1h, a1l);
        split2(*reinterpret_cast<const float2*>(Qr0 + 2 * kp + 8), a2h, a2l);
        split2(*reinterpret_cast<const float2*>(Qr1 + 2 * kp + 8), a3h, a3l);
        #pragma unroll
        for (int nt = 0; nt < 4; nt++) {
            const float* Kr = K + (n0 + nt * 8 + gid) * ST + ch0;
            uint32_t b0h, b0l, b1h, b1l;
            split2(*reinterpret_cast<const float2*>(Kr + 2 * kp), b0h, b0l);
            split2(*reinterpret_cast<const float2*>(Kr + 2 * kp + 8), b1h, b1l);
            mma16(d[nt], a0h, a1h, a2h, a3h, b0h, b1h);
            mma16(d[nt], a0h, a1h, a2h, a3h, b0l, b1l);
            mma16(d[nt], a0l, a1l, a2l, a3l, b0h, b1h);
        }
    }
    const int r0 = m0 + gid, r1 = r0 + 8;
    const int i0r = r0 / 7, i0c = r0 % 7;
    const int i1r = r1 / 7, i1c = r1 % 7;
    #pragma unroll
    for (int nt = 0; nt < 4; nt++) {
        #pragma unroll
        for (int c = 0; c < 2; c++) {
            int j = n0 + nt * 8 + tig * 2 + c;
            if (j < NTOK) {
                int jr = j / 7, jc = j % 7;
                if (r0 < NTOK)
                    SCR[r0 * AST + j] = d[nt][c] * SCALEF
                        + RPB[((i0r - jr + 6) * 13 + (i0c - jc + 6)) * 3 + h];
                if (r1 < NTOK)
                    SCR[r1 * AST + j] = d[nt][2 + c] * SCALEF
                        + RPB[((i1r - jr + 6) * 13 + (i1c - jc + 6)) * 3 + h];
            }
        }
    }
}

// ---- attn@V via MMA ---------------------------------------------------------
__device__ __forceinline__ void attnv_mma(const float* SCR, const float* V,
                                          float* O, int h, int warp, int lane)
{
    const int ch0 = h * HDIM;
    const int m0 = (warp >> 1) * 16;
    const int n0 = (warp & 1) * 16;
    const int gid = lane >> 2, tig = lane & 3;
    float d[2][4];
    #pragma unroll
    for (int i = 0; i < 2; i++) { d[i][0] = d[i][1] = d[i][2] = d[i][3] = 0.f; }
    const float* Pr0 = SCR + (m0 + gid) * AST;
    const float* Pr1 = Pr0 + 8 * AST;
    #pragma unroll
    for (int kc = 0; kc < 4; kc++) {
        const int k0 = 2 * (kc * 8 + tig);
        const int k2 = k0 + 8;
        uint32_t a0h = 0, a0l = 0, a1h = 0, a1l = 0;
        uint32_t a2h = 0, a2l = 0, a3h = 0, a3l = 0;
        if (k0 <= 48) {
            split2(*reinterpret_cast<const float2*>(Pr0 + k0), a0h, a0l);
            split2(*reinterpret_cast<const float2*>(Pr1 + k0), a1h, a1l);
        }
        if (k2 <= 48) {
            split2(*reinterpret_cast<const float2*>(Pr0 + k2), a2h, a2l);
            split2(*reinterpret_cast<const float2*>(Pr1 + k2), a3h, a3l);
        }
        #pragma unroll
        for (int nt = 0; nt < 2; nt++) {
            const int n = ch0 + n0 + nt * 8 + gid;
            uint32_t b0h, b0l, b1h, b1l;
            split2(make_float2(V[k0 * ST + n], V[(k0 + 1) * ST + n]), b0h, b0l);
            split2(make_float2(V[k2 * ST + n], V[(k2 + 1) * ST + n]), b1h, b1l);
            mma16(d[nt], a0h, a1h, a2h, a3h, b0h, b1h);
            mma16(d[nt], a0h, a1h, a2h, a3h, b0l, b1l);
            mma16(d[nt], a0l, a1l, a2l, a3l, b0h, b1h);
        }
    }
    const int r0 = m0 + gid, r1 = r0 + 8;
    #pragma unroll
    for (int nt = 0; nt < 2; nt++) {
        int n = ch0 + n0 + nt * 8 + tig * 2;
        if (r0 < NTOK)
            *reinterpret_cast<float2*>(O + r0 * ST + n) = make_float2(d[nt][0], d[nt][1]);
        if (r1 < NTOK)
            *reinterpret_cast<float2*>(O + r1 * ST + n) = make_float2(d[nt][2], d[nt][3]);
    }
}

// ---- cattn via MMA: CAT[h][d][e] = SCALE*invNK[d]*invNQ[e]*sum_t ks[t][d]qs[t][e]
// M=d(32), N=e(32), K=t(64 pad, both operands zeroed for t>=49). 6 warps.
__device__ __forceinline__ void cattn_mma(const float* QS, const float* KS,
                                          float* CAT, const float* NQ, const float* NK,
                                          int warp, int lane)
{
    if (warp >= 6) return;
    const int h = warp >> 1, mt = warp & 1;
    const int ch = h * HDIM, m0 = mt * 16;
    const int gid = lane >> 2, tig = lane & 3;
    float d[4][4];
    #pragma unroll
    for (int i = 0; i < 4; i++) { d[i][0] = d[i][1] = d[i][2] = d[i][3] = 0.f; }
    #pragma unroll
    for (int kc = 0; kc < 4; kc++) {
        const int k0 = 2 * (kc * 8 + tig);
        const int k1 = k0 + 1, k2 = k0 + 8, k3 = k0 + 9;
        const int ca = ch + m0 + gid;
        float a00 = (k0 < NTOK) ? KS[k0 * ST + ca] : 0.f;
        float a01 = (k1 < NTOK) ? KS[k1 * ST + ca] : 0.f;
        float a10 = (k0 < NTOK) ? KS[k0 * ST + ca + 8] : 0.f;
        float a11 = (k1 < NTOK) ? KS[k1 * ST + ca + 8] : 0.f;
        float a20 = (k2 < NTOK) ? KS[k2 * ST + ca] : 0.f;
        float a21 = (k3 < NTOK) ? KS[k3 * ST + ca] : 0.f;
        float a30 = (k2 < NTOK) ? KS[k2 * ST + ca + 8] : 0.f;
        float a31 = (k3 < NTOK) ? KS[k3 * ST + ca + 8] : 0.f;
        uint32_t a0h, a0l, a1h, a1l, a2h, a2l, a3h, a3l;
        split2(make_float2(a00, a01), a0h, a0l);
        split2(make_float2(a10, a11), a1h, a1l);
        split2(make_float2(a20, a21), a2h, a2l);
        split2(make_float2(a30, a31), a3h, a3l);
        #pragma unroll
        for (int nt = 0; nt < 4; nt++) {
            const int ce = ch + nt * 8 + gid;
            float b00 = (k0 < NTOK) ? QS[k0 * ST + ce] : 0.f;
            float b01 = (k1 < NTOK) ? QS[k1 * ST + ce] : 0.f;
            float b10 = (k2 < NTOK) ? QS[k2 * ST + ce] : 0.f;
            float b11 = (k3 < NTOK) ? QS[k3 * ST + ce] : 0.f;
            uint32_t b0h, b0l, b1h, b1l;
            split2(make_float2(b00, b01), b0h, b0l);
            split2(make_float2(b10, b11), b1h, b1l);
            mma16(d[nt], a0h, a1h, a2h, a3h, b0h, b1h);
            mma16(d[nt], a0h, a1h, a2h, a3h, b0l, b1l);
            mma16(d[nt], a0l, a1l, a2l, a3l, b0h, b1h);
        }
    }
    const int r0 = m0 + gid, r1 = r0 + 8;
    const float sk0 = NK[ch + r0] * SCALEF;
    const float sk1 = NK[ch + r1] * SCALEF;
    float* C0 = CAT + h * 1088 + r0 * CST;
    float* C1 = CAT + h * 1088 + r1 * CST;
    #pragma unroll
    for (int nt = 0; nt < 4; nt++) {
        int e0 = nt * 8 + tig * 2;
        float q0 = NQ[ch + e0], q1 = NQ[ch + e0 + 1];
        C0[e0]     = d[nt][0] * sk0 * q0;
        C0[e0 + 1] = d[nt][1] * sk0 * q1;
        C1[e0]     = d[nt][2] * sk1 * q0;
        C1[e0 + 1] = d[nt][3] * sk1 * q1;
    }
}

// ---- xc via MMA: O[t][ch+d] = sum_e CAT[h][d][e] * V[t][ch+e] --------------
// M=t(64, stores guarded), N=d(32), K=e(32). 12 slots over 8 warps.
__device__ __forceinline__ void xc_mma(const float* CAT, const float* V, float* O,
                                       int warp, int lane)
{
    const int gid = lane >> 2, tig = lane & 3;
    for (int slot = warp; slot < 12; slot += 8) {
        const int h = slot >> 2, mt = slot & 3;
        const int ch = h * HDIM, m0 = mt * 16;
        float d[4][4];
        #pragma unroll
        for (int i = 0; i < 4; i++) { d[i][0] = d[i][1] = d[i][2] = d[i][3] = 0.f; }
        const float* Ar0 = V + (m0 + gid) * ST + ch;
        const float* Ar1 = Ar0 + 8 * ST;
        #pragma unroll
        for (int kc = 0; kc < 2; kc++) {
            const int kp = kc * 8 + tig;
            uint32_t a0h, a0l, a1h, a1l, a2h, a2l, a3h, a3l;
            split2(*reinterpret_cast<const float2*>(Ar0 + 2 * kp), a0h, a0l);
            split2(*reinterpret_cast<const float2*>(Ar1 + 2 * kp), a1h, a1l);
            split2(*reinterpret_cast<const float2*>(Ar0 + 2 * kp + 8), a2h, a2l);
            split2(*reinterpret_cast<const float2*>(Ar1 + 2 * kp + 8), a3h, a3l);
            #pragma unroll
            for (int nt = 0; nt < 4; nt++) {
                const float* Br = CAT + h * 1088 + (nt * 8 + gid) * CST;
                uint32_t b0h, b0l, b1h, b1l;
                split2(*reinterpret_cast<const float2*>(Br + 2 * kp), b0h, b0l);
                split2(*reinterpret_cast<const float2*>(Br + 2 * kp + 8), b1h, b1l);
                mma16(d[nt], a0h, a1h, a2h, a3h, b0h, b1h);
                mma16(d[nt], a0h, a1h, a2h, a3h, b0l, b1l);
                mma16(d[nt], a0l, a1l, a2l, a3l, b0h, b1h);
            }
        }
        const int r0 = m0 + gid, r1 = r0 + 8;
        #pragma unroll
        for (int nt = 0; nt < 4; nt++) {
            int n = ch + nt * 8 + tig * 2;
            if (r0 < NTOK)
                *reinterpret_cast<float2*>(O + r0 * ST + n) = make_float2(d[nt][0], d[nt][1]);
            if (r1 < NTOK)
                *reinterpret_cast<float2*>(O + r1 * ST + n) = make_float2(d[nt][2], d[nt][3]);
        }
    }
}

// ---- depthwise 3x3 conv -----------------------------------------------------
__device__ __forceinline__ void dwconv5(const float* In, const float* __restrict__ Wc,
                                        float* Out, int tid, int mode)
{
    if (tid >= 240) return;
    const int c0 = (tid / 10) * 4, t0 = (tid % 10) * 5;
    u64 wc[9][2];
    #pragma unroll
    for (int s = 0; s < 9; s++) {
        const ulonglong2* wp = reinterpret_cast<const ulonglong2*>(Wc + s * 96 + c0);
        ulonglong2 w = *wp;
        wc[s][0] = w.x; wc[s][1] = w.y;
    }
    #pragma unroll
    for (int tt = 0; tt < 5; tt++) {
        int t = t0 + tt;
        if (t >= NTOK) break;
        int r = t / 7, cc = t % 7;
        u64 a0 = 0ULL, a1 = 0ULL;
        #pragma unroll
        for (int dr = 0; dr < 3; dr++) {
            int rr = r + dr - 1;
            if (rr < 0 || rr > 6) continue;
            #pragma unroll
            for (int dc = 0; dc < 3; dc++) {
                int c2 = cc + dc - 1;
                if (c2 < 0 || c2 > 6) continue;
                const float* vp = In + (rr * 7 + c2) * ST + c0;
                fma2(a0, lds64(vp), wc[dr * 3 + dc][0]);
                fma2(a1, lds64(vp + 2), wc[dr * 3 + dc][1]);
            }
        }
        float2 p0 = unp(a0), p1 = unp(a1);
        float* o = Out + t * ST + c0;
        if (mode == 0) {
            o[0] = 0.5f * p0.x * (1.f + erff(p0.x * 0.70710678118654752f));
            o[1] = 0.5f * p0.y * (1.f + erff(p0.y * 0.70710678118654752f));
            o[2] = 0.5f * p1.x * (1.f + erff(p1.x * 0.70710678118654752f));
            o[3] = 0.5f * p1.y * (1.f + erff(p1.y * 0.70710678118654752f));
        } else {
            o[0] += p0.x; o[1] += p0.y; o[2] += p1.x; o[3] += p1.y;
        }
    }
}

__global__ __launch_bounds__(NTHR, 2) void winattn_kernel(
    const float* __restrict__ x,
    const float* __restrict__ rpb_table,
    const float* __restrict__ bq,  const float* __restrict__ bk,
    const float* __restrict__ bv,  const float* __restrict__ b_ps,
    const float* __restrict__ b_pc,
    const float* __restrict__ conv1, const float* __restrict__ conv2,
    const float* __restrict__ b_proj,
    float* __restrict__ out)
{
    extern __shared__ float sm[];
    float* A   = sm + OFF_A;
    float* Bb  = sm + OFF_B;
    float* Cc  = sm + OFF_C;
    float* Dd  = sm + OFF_D;
    float* Ee  = sm + OFF_E;
    float* RPB = sm + OFF_RPB;
    float* NQ  = sm + OFF_NQ;
    float* NK  = sm + OFF_NK;
    float* CAT = sm + OFF_CAT;

    const int tid  = threadIdx.x;
    const int blk  = blockIdx.x;
    const int warp = tid >> 5, lane = tid & 31;

    {
        const float4* xg4 = reinterpret_cast<const float4*>(x + (size_t)blk * (NTOK * NCH));
        for (int i4 = tid; i4 < NTOK * 24; i4 += NTHR) {
            float4 v = xg4[i4];
            int t = i4 / 24, c = (i4 % 24) * 4;
            float* p = A + t * ST + c;
            p[0] = v.x; p[1] = v.y; p[2] = v.z; p[3] = v.w;
        }
        for (int i = tid; i < 507; i += NTHR) RPB[i] = rpb_table[i];
    }
    __syncthreads();

    // ---- q, k, v projections (independent: one barrier) ----
    gemm_bf16(A, 0 * FRAG_PER_G, bq, Bb, warp, lane);
    gemm_bf16(A, 1 * FRAG_PER_G, bk, Cc, warp, lane);
    gemm_bf16(A, 2 * FRAG_PER_G, bv, Dd, warp, lane);
    __syncthreads();

    // ---- spatial attention, per head (all-MMA) ----
    for (int h = 0; h < NHEADS; h++) {
        scores_mma(Bb, Cc, Ee, RPB, h, warp, lane);
        __syncthreads();
        for (int r = warp; r < NTOK; r += 8) {
            float* row = Ee + r * AST;
            float e1 = row[lane];
            bool hi = (lane + 32) < NTOK;
            float e2 = hi ? row[lane + 32] : -3.4e38f;
            float m = fmaxf(e1, e2);
            #pragma unroll
            for (int o = 16; o > 0; o >>= 1) m = fmaxf(m, __shfl_xor_sync(0xffffffffu, m, o));
            float p1 = __expf(e1 - m);
            float p2 = hi ? __expf(e2 - m) : 0.f;
            float s = p1 + p2;
            #pragma unroll
            for (int o = 16; o > 0; o >>= 1) s += __shfl_xor_sync(0xffffffffu, s, o);
            float inv = 1.f / s;
            row[lane] = p1 * inv;
            if (hi) row[lane + 32] = p2 * inv;
            if (lane == 0) row[NTOK] = 0.f;
        }
        __syncthreads();
        attnv_mma(Ee, Dd, Bb, h, warp, lane);
        __syncthreads();
    }

    // ---- {spatial = sp @ w_ps -> C} and {qs = x @ wq_sp -> E} ----
    gemm_bf16(Bb, 3 * FRAG_PER_G, b_ps, Cc, warp, lane);
    gemm_bf16(A, 4 * FRAG_PER_G, 0, Ee, warp, lane);
    __syncthreads();
    // ---- ks = x @ wk_sp -> B ----
    gemm_bf16(A, 5 * FRAG_PER_G, 0, Bb, warp, lane);
    __syncthreads();

    // ---- inverse L2 norms per channel ----
    if (tid < 96) {
        float s = 0.f;
        for (int t = 0; t < NTOK; t++) { float v = Ee[t * ST + tid]; s += v * v; }
        NQ[tid] = rsqrtf(fmaxf(s, 1e-24f));
    } else if (tid < 192) {
        int c = tid - 96;
        float s = 0.f;
        for (int t = 0; t < NTOK; t++) { float v = Bb[t * ST + c]; s += v * v; }
        NK[c] = rsqrtf(fmaxf(s, 1e-24f));
    }
    __syncthreads();

    // ---- cattn raw + normalize (MMA, ks=B, qs=E) ----
    cattn_mma(Ee, Bb, CAT, NQ, NK, warp, lane);
    __syncthreads();
    // ---- cattn softmax: warp per row, 96 rows of 32 (8 warps) ----
    for (int rid = warp; rid < 96; rid += 8) {
        float* row = CAT + (rid >> 5) * 1088 + (rid & 31) * CST;
        float e = row[lane];
        float m = e;
        #pragma unroll
        for (int o = 16; o > 0; o >>= 1) m = fmaxf(m, __shfl_xor_sync(0xffffffffu, m, o));
        float p = __expf(e - m);
        float s = p;
        #pragma unroll
        for (int o = 16; o > 0; o >>= 1) s += __shfl_xor_sync(0xffffffffu, s, o);
        row[lane] = p * (1.f / s);
    }
    __syncthreads();

    // ---- xc = cattn @ v -> A (MMA) ----
    xc_mma(CAT, Dd, A, warp, lane);
    __syncthreads();

    // ---- {out_c = xc @ w_pc -> E} and {conv1(v)+GELU -> B} (independent) ----
    gemm_bf16(A, 6 * FRAG_PER_G, b_pc, Ee, warp, lane);
    dwconv5(Dd, conv1, Bb, tid, 0);
    __syncthreads();

    // ---- conv2(gelu) -> E += ----
    dwconv5(Bb, conv2, Ee, tid, 1);
    __syncthreads();

    // ---- final projection ----
    proj_bf16(Cc, Ee, b_proj, out + (size_t)blk * (NTOK * NCH), warp, lane);
}

extern "C" void kernel_launch(void* const* d_in, const int* in_sizes, int n_in,
                              void* d_out, int out_size)
{
    const float* x      = (const float*)d_in[0];
    const float* rpb    = (const float*)d_in[1];
    const float* wq     = (const float*)d_in[2];
    const float* bq     = (const float*)d_in[3];
    const float* wk     = (const float*)d_in[4];
    const float* bk     = (const float*)d_in[5];
    const float* wv     = (const float*)d_in[6];
    const float* bv     = (const float*)d_in[7];
    const float* w_ps   = (const float*)d_in[8];
    const float* b_ps   = (const float*)d_in[9];
    const float* wq_sp  = (const float*)d_in[10];
    const float* wk_sp  = (const float*)d_in[11];
    const float* w_pc   = (const float*)d_in[12];
    const float* b_pc   = (const float*)d_in[13];
    const float* conv1  = (const float*)d_in[14];
    const float* conv2  = (const float*)d_in[15];
    const float* w_proj = (const float*)d_in[16];
    const float* b_proj = (const float*)d_in[17];
    float* out = (float*)d_out;

    int nwin = in_sizes[0] / (NTOK * NCH);

    prep_weights<<<(NFRAG + 255) / 256, 256>>>(wq, wk, wv, w_ps, wq_sp, wk_sp, w_pc, w_proj);

    cudaFuncSetAttribute(winattn_kernel,
                         cudaFuncAttributeMaxDynamicSharedMemorySize, SMEM_BYTES);
    winattn_kernel<<<nwin, NTHR, SMEM_BYTES>>>(
        x, rpb, bq, bk, bv, b_ps, b_pc, conv1, conv2, b_proj, out);
}